// round 2
// baseline (speedup 1.0000x reference)
#include <cuda_runtime.h>
#include <math.h>

#define DDIM 256
#define MMAX 50000

// scratch: tanh(concat(trans_ho[p], trans_hp[p], trans_hk[k]))  [M, 768]
__device__ float g_tanhbuf[(size_t)MMAX * 3 * DDIM];

// ---------------------------------------------------------------------------
// GEMM: C[r, colOff + j] = sum_k A[row(r), k] * W[k, j]   (K = 256, W is [256,256])
// BM=64, BN=64, BK=16, 256 threads, 4x4 per thread.
// GATHER: row(r) = rowmap[r], else identity. TANH: apply tanhf to outputs.
// ---------------------------------------------------------------------------
template<bool GATHER, bool TANH>
__global__ void __launch_bounds__(256) gemm256_k(
    const float* __restrict__ A, const float* __restrict__ W,
    float* __restrict__ C, int rowsC, int ldc, int colOff,
    const int* __restrict__ rowmap)
{
    const int BM = 64, BN = 64, BK = 16;
    __shared__ float As[BK][BM];
    __shared__ float Bs[BK][BN];

    const int rowBase = blockIdx.y * BM;
    const int colBase = blockIdx.x * BN;
    const int tid = threadIdx.x;
    const int ty = tid >> 4;         // 0..15
    const int tx = tid & 15;         // 0..15

    float acc[4][4];
    #pragma unroll
    for (int i = 0; i < 4; i++)
        #pragma unroll
        for (int j = 0; j < 4; j++) acc[i][j] = 0.0f;

    const int aLocalRow = tid >> 2;
    const int aSeg = (tid & 3) * 4;
    const int aRow = rowBase + aLocalRow;
    const float* Aptr = nullptr;
    if (aRow < rowsC) {
        int src = GATHER ? rowmap[aRow] : aRow;
        Aptr = A + (size_t)src * DDIM + aSeg;
    }
    const int bk = tid >> 4;
    const int bj = (tid & 15) * 4;

    for (int k0 = 0; k0 < DDIM; k0 += BK) {
        float4 av = make_float4(0.f, 0.f, 0.f, 0.f);
        if (Aptr) av = *(const float4*)(Aptr + k0);
        As[aSeg + 0][aLocalRow] = av.x;
        As[aSeg + 1][aLocalRow] = av.y;
        As[aSeg + 2][aLocalRow] = av.z;
        As[aSeg + 3][aLocalRow] = av.w;

        float4 bv = *(const float4*)(W + (size_t)(k0 + bk) * DDIM + colBase + bj);
        *(float4*)&Bs[bk][bj] = bv;
        __syncthreads();

        #pragma unroll
        for (int kk = 0; kk < BK; kk++) {
            float4 a = *(const float4*)&As[kk][ty * 4];
            float4 b = *(const float4*)&Bs[kk][tx * 4];
            float ar[4] = {a.x, a.y, a.z, a.w};
            float br[4] = {b.x, b.y, b.z, b.w};
            #pragma unroll
            for (int i = 0; i < 4; i++)
                #pragma unroll
                for (int j = 0; j < 4; j++)
                    acc[i][j] += ar[i] * br[j];
        }
        __syncthreads();
    }

    #pragma unroll
    for (int i = 0; i < 4; i++) {
        int r = rowBase + ty * 4 + i;
        if (r >= rowsC) continue;
        float4 v;
        v.x = acc[i][0]; v.y = acc[i][1]; v.z = acc[i][2]; v.w = acc[i][3];
        if (TANH) {
            v.x = tanhf(v.x); v.y = tanhf(v.y); v.z = tanhf(v.z); v.w = tanhf(v.w);
        }
        *(float4*)&C[(size_t)r * ldc + colOff + colBase + tx * 4] = v;
    }
}

// ---------------------------------------------------------------------------
// Gather trans_hp[p], trans_hk[k] rows from d_out, tanh, write into scratch
// cols [256:512) and [512:768).
// ---------------------------------------------------------------------------
__global__ void gather_tanh_k(const float* __restrict__ out,
                              const int* __restrict__ idxP,
                              const int* __restrict__ idxK,
                              float* __restrict__ tbuf,
                              int Mr, int Nr)
{
    int i = blockIdx.x * blockDim.x + threadIdx.x;
    int m = i >> 6;
    int c4 = (i & 63) * 4;
    if (m >= Mr) return;
    int p = idxP[m];
    int kq = idxK[m];
    float4 v = *(const float4*)&out[(size_t)p * DDIM + c4];
    v.x = tanhf(v.x); v.y = tanhf(v.y); v.z = tanhf(v.z); v.w = tanhf(v.w);
    *(float4*)&tbuf[(size_t)m * 768 + 256 + c4] = v;
    float4 w = *(const float4*)&out[(size_t)Nr * DDIM + (size_t)kq * DDIM + c4];
    w.x = tanhf(w.x); w.y = tanhf(w.y); w.z = tanhf(w.z); w.w = tanhf(w.w);
    *(float4*)&tbuf[(size_t)m * 768 + 512 + c4] = w;
}

// ---------------------------------------------------------------------------
// Final: out2[m, j] = leaky(sum_t T[m,t] * L[j,t] + linear_b[j]) + bias[j]
// scattered into d_out at rows idxP[m] (hp half) and idxK[m] (hk half).
// ---------------------------------------------------------------------------
__global__ void __launch_bounds__(256) gemm_final_k(
    const float* __restrict__ T,
    const float* __restrict__ L,
    const float* __restrict__ linear_b,
    const float* __restrict__ bias,
    float* __restrict__ out, int Mr, int Nr,
    const int* __restrict__ idxP, const int* __restrict__ idxK)
{
    const int BM = 64, BN = 64, BK = 16;
    const int KDIM = 768;
    __shared__ float As[BK][BM];
    __shared__ float Bs[BK][BN];

    const int rowBase = blockIdx.y * BM;
    const int colBase = blockIdx.x * BN;
    const int tid = threadIdx.x;
    const int ty = tid >> 4;
    const int tx = tid & 15;

    float acc[4][4];
    #pragma unroll
    for (int i = 0; i < 4; i++)
        #pragma unroll
        for (int j = 0; j < 4; j++) acc[i][j] = 0.0f;

    const int aLocalRow = tid >> 2;
    const int aSeg = (tid & 3) * 4;
    const int aRow = rowBase + aLocalRow;
    const float* Aptr = (aRow < Mr) ? (T + (size_t)aRow * KDIM + aSeg) : nullptr;

    const int bLocalJ = tid >> 2;
    const int bSeg = (tid & 3) * 4;

    for (int k0 = 0; k0 < KDIM; k0 += BK) {
        float4 av = make_float4(0.f, 0.f, 0.f, 0.f);
        if (Aptr) av = *(const float4*)(Aptr + k0);
        As[aSeg + 0][aLocalRow] = av.x;
        As[aSeg + 1][aLocalRow] = av.y;
        As[aSeg + 2][aLocalRow] = av.z;
        As[aSeg + 3][aLocalRow] = av.w;

        float4 lv = *(const float4*)(L + (size_t)(colBase + bLocalJ) * KDIM + k0 + bSeg);
        Bs[bSeg + 0][bLocalJ] = lv.x;
        Bs[bSeg + 1][bLocalJ] = lv.y;
        Bs[bSeg + 2][bLocalJ] = lv.z;
        Bs[bSeg + 3][bLocalJ] = lv.w;
        __syncthreads();

        #pragma unroll
        for (int kk = 0; kk < BK; kk++) {
            float4 a = *(const float4*)&As[kk][ty * 4];
            float4 b = *(const float4*)&Bs[kk][tx * 4];
            float ar[4] = {a.x, a.y, a.z, a.w};
            float br[4] = {b.x, b.y, b.z, b.w};
            #pragma unroll
            for (int i = 0; i < 4; i++)
                #pragma unroll
                for (int j = 0; j < 4; j++)
                    acc[i][j] += ar[i] * br[j];
        }
        __syncthreads();
    }

    #pragma unroll
    for (int i = 0; i < 4; i++) {
        int r = rowBase + ty * 4 + i;
        if (r >= Mr) continue;
        int p = idxP[r];
        int kq = idxK[r];
        int jBase = colBase + tx * 4;
        float4 v;
        float* av = &v.x;
        #pragma unroll
        for (int j = 0; j < 4; j++) {
            float x = acc[i][j] + linear_b[jBase + j];
            x = (x > 0.0f) ? x : 0.01f * x;
            av[j] = x + bias[jBase + j];
        }
        *(float4*)&out[(size_t)p * DDIM + jBase] = v;
        *(float4*)&out[(size_t)Nr * DDIM + (size_t)kq * DDIM + jBase] = v;
    }
}

extern "C" void kernel_launch(void* const* d_in, const int* in_sizes, int n_in,
                              void* d_out, int out_size)
{
    const float* h_p = (const float*)d_in[0];
    const float* h_k = (const float*)d_in[1];
    const float* h_o = (const float*)d_in[2];
    const int* idxP  = (const int*)d_in[3];
    const int* idxK  = (const int*)d_in[4];
    const float* w_o = (const float*)d_in[5];
    const float* w_p = (const float*)d_in[6];
    const float* w_k = (const float*)d_in[7];
    const float* lw  = (const float*)d_in[8];   // [256, 768]
    const float* lb  = (const float*)d_in[9];   // [256]
    const float* bs  = (const float*)d_in[10];  // [256]
    float* out = (float*)d_out;                  // [2, N, 256]

    const int N = in_sizes[0] / DDIM;
    const int M = in_sizes[3];

    // CRITICAL: device address of the __device__ scratch buffer. Referencing
    // g_tanhbuf directly in host code yields the host shadow address (which
    // GB300's ATS happily lets kernels write into — silently wrong).
    float* tbuf = nullptr;
    cudaGetSymbolAddress((void**)&tbuf, g_tanhbuf);

    dim3 blk(256);
    // full GEMMs: trans_hp -> out[0:N*D), trans_hk -> out[N*D:2N*D)
    {
        dim3 grd(DDIM / 64, (N + 63) / 64);
        gemm256_k<false, false><<<grd, blk>>>(h_p, w_p, out, N, DDIM, 0, nullptr);
        gemm256_k<false, false><<<grd, blk>>>(h_k, w_k, out + (size_t)N * DDIM, N, DDIM, 0, nullptr);
    }
    // gathered ho GEMM with fused tanh -> scratch cols [0:256)
    {
        dim3 grd(DDIM / 64, (M + 63) / 64);
        gemm256_k<true, true><<<grd, blk>>>(h_o, w_o, tbuf, M, 768, 0, idxP);
    }
    // gather + tanh of trans rows -> scratch cols [256:768)
    {
        int total = M * 64;
        gather_tanh_k<<<(total + 255) / 256, 256>>>(out, idxP, idxK, tbuf, M, N);
    }
    // final linear + leaky_relu + bias + scatter
    {
        dim3 grd(DDIM / 64, (M + 63) / 64);
        gemm_final_k<<<grd, blk>>>(tbuf, lw, lb, bs, out, M, N, idxP, idxK);
    }
}

// round 5
// speedup vs baseline: 2.1875x; 2.1875x over previous
#include <cuda_runtime.h>
#include <cuda_bf16.h>
#include <math.h>
#include <stdint.h>

#define DDIM 256
#define NMAX 100000
#define MMAX 50000

// ---------------- device scratch (static; no runtime allocs) ---------------
__device__ __nv_bfloat16 g_Whi[3 * 256 * 256];   // transposed [n][k] hi
__device__ __nv_bfloat16 g_Wlo[3 * 256 * 256];   // transposed [n][k] lo
__device__ __nv_bfloat16 g_Lhi[256 * 768];       // linear_w [n][k]
__device__ __nv_bfloat16 g_Llo[256 * 768];
__device__ __nv_bfloat16 g_Thi[(size_t)MMAX * 768];  // tanh concat hi
__device__ __nv_bfloat16 g_Tlo[(size_t)MMAX * 768];  // tanh concat lo
__device__ __nv_bfloat16 g_Ahp_hi[(size_t)NMAX * 256];
__device__ __nv_bfloat16 g_Ahp_lo[(size_t)NMAX * 256];
__device__ __nv_bfloat16 g_Ahk_hi[(size_t)NMAX * 256];
__device__ __nv_bfloat16 g_Ahk_lo[(size_t)NMAX * 256];
__device__ __nv_bfloat16 g_Aho_hi[(size_t)MMAX * 256];
__device__ __nv_bfloat16 g_Aho_lo[(size_t)MMAX * 256];

// ---------------- helpers --------------------------------------------------
__device__ __forceinline__ uint32_t smem_u32(const void* p) {
    uint32_t a;
    asm("{ .reg .u64 t; cvta.to.shared.u64 t, %1; cvt.u32.u64 %0, t; }" : "=r"(a) : "l"(p));
    return a;
}
__device__ __forceinline__ void ldmx4(uint32_t& r0, uint32_t& r1, uint32_t& r2, uint32_t& r3,
                                      uint32_t addr) {
    asm volatile("ldmatrix.sync.aligned.m8n8.x4.shared.b16 {%0,%1,%2,%3}, [%4];"
                 : "=r"(r0), "=r"(r1), "=r"(r2), "=r"(r3) : "r"(addr));
}
__device__ __forceinline__ void ldmx2(uint32_t& r0, uint32_t& r1, uint32_t addr) {
    asm volatile("ldmatrix.sync.aligned.m8n8.x2.shared.b16 {%0,%1}, [%2];"
                 : "=r"(r0), "=r"(r1) : "r"(addr));
}
__device__ __forceinline__ void mma16816(float* d, uint32_t a0, uint32_t a1, uint32_t a2,
                                         uint32_t a3, uint32_t b0, uint32_t b1) {
    asm volatile(
        "mma.sync.aligned.m16n8k16.row.col.f32.bf16.bf16.f32 "
        "{%0,%1,%2,%3}, {%4,%5,%6,%7}, {%8,%9}, {%0,%1,%2,%3};"
        : "+f"(d[0]), "+f"(d[1]), "+f"(d[2]), "+f"(d[3])
        : "r"(a0), "r"(a1), "r"(a2), "r"(a3), "r"(b0), "r"(b1));
}
#define SW128(o) ((o) ^ (((o) >> 3) & 0x70))

__device__ __forceinline__ void split_bf(float x, __nv_bfloat16& h, __nv_bfloat16& l) {
    h = __float2bfloat16_rn(x);
    l = __float2bfloat16_rn(x - __bfloat162float(h));
}

// smem: Ahi[128][64] Alo Bhi[128][64] Blo, each 16KB (128B SW128 rows)
#define OFF_AHI 0
#define OFF_ALO 16384
#define OFF_BHI 32768
#define OFF_BLO 49152
#define SMEM_BYTES 65536

struct Args {
    const __nv_bfloat16* Ahi;
    const __nv_bfloat16* Alo;
    const __nv_bfloat16* Bhi;
    const __nv_bfloat16* Blo;
    float* outF;
    __nv_bfloat16* Thi;
    __nv_bfloat16* Tlo;
    const int* idxP;
    const int* idxK;
    const float* lb;
    const float* bias;
    int rowsC;
    int Nfull;
};

// EPI: 0 = store fp32 rows to outF; 1 = tanh -> Thi/Tlo (cols 0..255 of T);
//      2 = +lb, leaky, +bias, scatter to outF rows idxP / Nfull+idxK
template<int EPI, int KDIM>
__global__ void __launch_bounds__(256, 2)
mma_gemm(const Args args)
{
    extern __shared__ char smem[];
    const uint32_t sb = smem_u32(smem);
    const int tid = threadIdx.x;
    const int w = tid >> 5;
    const int lane = tid & 31;
    const int rowBase = blockIdx.x * 128;
    const int colBase = blockIdx.y * 128;
    const int rowsC = args.rowsC;

    const int wm = w & 1;         // 2 m-tiles of 64
    const int wn = w >> 1;        // 4 n-tiles of 32

    float acc[64];                // [mf][nf][4]
    #pragma unroll
    for (int i = 0; i < 64; i++) acc[i] = 0.0f;

    const int NCH = KDIM / 64;
    for (int c = 0; c < NCH; c++) {
        const int k0 = c * 64;
        // ---- fill A tiles (128 rows x 64 k, bf16 hi/lo) ----
        #pragma unroll
        for (int i = 0; i < 4; i++) {
            int q = tid + i * 256;       // 0..1023
            int r = q >> 3;
            int j8 = (q & 7) * 8;
            uint32_t so = SW128((uint32_t)(r * 128 + j8 * 2));
            uint4 vh = make_uint4(0, 0, 0, 0), vl = vh;
            int gr = rowBase + r;
            if (gr < rowsC) {
                size_t off = (size_t)gr * KDIM + k0 + j8;
                vh = *(const uint4*)(args.Ahi + off);
                vl = *(const uint4*)(args.Alo + off);
            }
            *(uint4*)(smem + OFF_AHI + so) = vh;
            *(uint4*)(smem + OFF_ALO + so) = vl;
        }
        // ---- fill B tiles (128 n-rows x 64 k), stride KDIM ----
        #pragma unroll
        for (int i = 0; i < 4; i++) {
            int q = tid + i * 256;
            int n = q >> 3;
            int j8 = (q & 7) * 8;
            size_t off = (size_t)(colBase + n) * KDIM + k0 + j8;
            uint32_t so = SW128((uint32_t)(n * 128 + j8 * 2));
            *(uint4*)(smem + OFF_BHI + so) = *(const uint4*)(args.Bhi + off);
            *(uint4*)(smem + OFF_BLO + so) = *(const uint4*)(args.Blo + off);
        }
        __syncthreads();

        #pragma unroll
        for (int ks = 0; ks < 4; ks++) {
            // B fragments for this k16 step
            uint32_t bh[4][2], bl[4][2];
            #pragma unroll
            for (int nf = 0; nf < 4; nf++) {
                int n = wn * 32 + nf * 8 + (lane & 7);
                uint32_t cby = (uint32_t)(ks * 32 + ((lane >> 3) & 1) * 16);
                uint32_t ad = sb + SW128((uint32_t)(n * 128) + cby);
                ldmx2(bh[nf][0], bh[nf][1], ad + OFF_BHI);
                ldmx2(bl[nf][0], bl[nf][1], ad + OFF_BLO);
            }
            #pragma unroll
            for (int mf = 0; mf < 4; mf++) {
                int m = wm * 64 + mf * 16 + (lane & 15);
                uint32_t cby = (uint32_t)(ks * 32 + (lane >> 4) * 16);
                uint32_t ad = sb + SW128((uint32_t)(m * 128) + cby);
                uint32_t ah0, ah1, ah2, ah3, al0, al1, al2, al3;
                ldmx4(ah0, ah1, ah2, ah3, ad + OFF_AHI);
                ldmx4(al0, al1, al2, al3, ad + OFF_ALO);
                #pragma unroll
                for (int nf = 0; nf < 4; nf++) {
                    float* d = &acc[mf * 16 + nf * 4];
                    mma16816(d, ah0, ah1, ah2, ah3, bh[nf][0], bh[nf][1]);
                    mma16816(d, ah0, ah1, ah2, ah3, bl[nf][0], bl[nf][1]);
                    mma16816(d, al0, al1, al2, al3, bh[nf][0], bh[nf][1]);
                }
            }
        }
        __syncthreads();
    }

    // ---- epilogue ----
    // thread t in warp: c0=(r,c) c1=(r,c+1) c2=(r+8,c) c3=(r+8,c+1)
    #pragma unroll
    for (int mf = 0; mf < 4; mf++) {
        int r0 = rowBase + wm * 64 + mf * 16 + (lane >> 2);
        #pragma unroll
        for (int half = 0; half < 2; half++) {
            int r = r0 + half * 8;
            if (r >= rowsC) continue;
            int pr = 0, kr = 0;
            if (EPI == 2) { pr = __ldg(args.idxP + r); kr = __ldg(args.idxK + r); }
            #pragma unroll
            for (int nf = 0; nf < 4; nf++) {
                int col = colBase + wn * 32 + nf * 8 + (lane & 3) * 2;
                float v0 = acc[mf * 16 + nf * 4 + half * 2 + 0];
                float v1 = acc[mf * 16 + nf * 4 + half * 2 + 1];
                if (EPI == 0) {
                    *(float2*)(args.outF + (size_t)r * 256 + col) = make_float2(v0, v1);
                } else if (EPI == 1) {
                    float t0 = tanhf(v0), t1 = tanhf(v1);
                    union { __nv_bfloat16 b[2]; uint32_t u; } h, l;
                    split_bf(t0, h.b[0], l.b[0]);
                    split_bf(t1, h.b[1], l.b[1]);
                    size_t off = (size_t)r * 768 + col;
                    *(uint32_t*)(args.Thi + off) = h.u;
                    *(uint32_t*)(args.Tlo + off) = l.u;
                } else {
                    float x0 = v0 + __ldg(args.lb + col);
                    float x1 = v1 + __ldg(args.lb + col + 1);
                    x0 = (x0 > 0.0f) ? x0 : 0.01f * x0;
                    x1 = (x1 > 0.0f) ? x1 : 0.01f * x1;
                    x0 += __ldg(args.bias + col);
                    x1 += __ldg(args.bias + col + 1);
                    float2 v = make_float2(x0, x1);
                    *(float2*)(args.outF + (size_t)pr * 256 + col) = v;
                    *(float2*)(args.outF + (size_t)(args.Nfull + kr) * 256 + col) = v;
                }
            }
        }
    }
}

// ---------------------------------------------------------------------------
// prep: transpose+split 3 weights [k][n]->[n][k] hi/lo; split linear_w [n][k]
// ---------------------------------------------------------------------------
__global__ void prep_k(const float* __restrict__ wo, const float* __restrict__ wp,
                       const float* __restrict__ wk, const float* __restrict__ lw,
                       __nv_bfloat16* __restrict__ Whi, __nv_bfloat16* __restrict__ Wlo,
                       __nv_bfloat16* __restrict__ Lhi, __nv_bfloat16* __restrict__ Llo)
{
    int idx = blockIdx.x * blockDim.x + threadIdx.x;
    if (idx < 3 * 65536) {
        int wi = idx >> 16;
        int e = idx & 65535;
        int k = e >> 8, n = e & 255;
        const float* W = (wi == 0) ? wo : ((wi == 1) ? wp : wk);
        float v = W[k * 256 + n];
        __nv_bfloat16 h, l;
        split_bf(v, h, l);
        Whi[wi * 65536 + n * 256 + k] = h;
        Wlo[wi * 65536 + n * 256 + k] = l;
    } else {
        int e = idx - 3 * 65536;
        if (e < 256 * 768) {
            __nv_bfloat16 h, l;
            split_bf(lw[e], h, l);
            Lhi[e] = h;
            Llo[e] = l;
        }
    }
}

// ---------------------------------------------------------------------------
// split fp32 rows -> bf16 hi/lo (optional gather)
// ---------------------------------------------------------------------------
__global__ void split_k(const float* __restrict__ src, const int* __restrict__ rowmap,
                        __nv_bfloat16* __restrict__ hi, __nv_bfloat16* __restrict__ lo,
                        int rows)
{
    int idx = blockIdx.x * blockDim.x + threadIdx.x;   // rows*32 items of 8
    int r = idx >> 5;
    int j8 = (idx & 31) * 8;
    if (r >= rows) return;
    int sr = rowmap ? __ldg(rowmap + r) : r;
    const float* ap = src + (size_t)sr * 256 + j8;
    float4 v0 = *(const float4*)ap;
    float4 v1 = *(const float4*)(ap + 4);
    float vv[8] = {v0.x, v0.y, v0.z, v0.w, v1.x, v1.y, v1.z, v1.w};
    union { __nv_bfloat16 b[8]; uint4 u; } uh, ul;
    #pragma unroll
    for (int j = 0; j < 8; j++) split_bf(vv[j], uh.b[j], ul.b[j]);
    size_t off = (size_t)r * 256 + j8;
    *(uint4*)(hi + off) = uh.u;
    *(uint4*)(lo + off) = ul.u;
}

// ---------------------------------------------------------------------------
// gather trans_hp/trans_hk rows, tanh, split into T cols [256:512),[512:768)
// ---------------------------------------------------------------------------
__global__ void gather_tanh_k(const float* __restrict__ out,
                              const int* __restrict__ idxP,
                              const int* __restrict__ idxK,
                              __nv_bfloat16* __restrict__ Thi,
                              __nv_bfloat16* __restrict__ Tlo,
                              int Mr, int Nr)
{
    int idx = blockIdx.x * blockDim.x + threadIdx.x;   // M*64 work items
    int m = idx >> 6;
    int part = idx & 63;
    if (m >= Mr) return;
    const float* src;
    int dcol;
    if (part < 32) {
        int p = __ldg(idxP + m);
        src = out + (size_t)p * 256 + part * 8;
        dcol = 256 + part * 8;
    } else {
        int kq = __ldg(idxK + m);
        src = out + (size_t)Nr * 256 + (size_t)kq * 256 + (part - 32) * 8;
        dcol = 512 + (part - 32) * 8;
    }
    float4 v0 = *(const float4*)src;
    float4 v1 = *(const float4*)(src + 4);
    float vv[8] = {v0.x, v0.y, v0.z, v0.w, v1.x, v1.y, v1.z, v1.w};
    union { __nv_bfloat16 b[8]; uint4 u; } uh, ul;
    #pragma unroll
    for (int j = 0; j < 8; j++) {
        float t = tanhf(vv[j]);
        split_bf(t, uh.b[j], ul.b[j]);
    }
    size_t off = (size_t)m * 768 + dcol;
    *(uint4*)(Thi + off) = uh.u;
    *(uint4*)(Tlo + off) = ul.u;
}

extern "C" void kernel_launch(void* const* d_in, const int* in_sizes, int n_in,
                              void* d_out, int out_size)
{
    const float* h_p = (const float*)d_in[0];
    const float* h_k = (const float*)d_in[1];
    const float* h_o = (const float*)d_in[2];
    const int* idxP  = (const int*)d_in[3];
    const int* idxK  = (const int*)d_in[4];
    const float* w_o = (const float*)d_in[5];
    const float* w_p = (const float*)d_in[6];
    const float* w_k = (const float*)d_in[7];
    const float* lw  = (const float*)d_in[8];
    const float* lb  = (const float*)d_in[9];
    const float* bs  = (const float*)d_in[10];
    float* out = (float*)d_out;

    const int N = in_sizes[0] / DDIM;
    const int M = in_sizes[3];

    __nv_bfloat16 *Whi, *Wlo, *Lhi, *Llo, *Thi, *Tlo;
    __nv_bfloat16 *AhpH, *AhpL, *AhkH, *AhkL, *AhoH, *AhoL;
    cudaGetSymbolAddress((void**)&Whi, g_Whi);
    cudaGetSymbolAddress((void**)&Wlo, g_Wlo);
    cudaGetSymbolAddress((void**)&Lhi, g_Lhi);
    cudaGetSymbolAddress((void**)&Llo, g_Llo);
    cudaGetSymbolAddress((void**)&Thi, g_Thi);
    cudaGetSymbolAddress((void**)&Tlo, g_Tlo);
    cudaGetSymbolAddress((void**)&AhpH, g_Ahp_hi);
    cudaGetSymbolAddress((void**)&AhpL, g_Ahp_lo);
    cudaGetSymbolAddress((void**)&AhkH, g_Ahk_hi);
    cudaGetSymbolAddress((void**)&AhkL, g_Ahk_lo);
    cudaGetSymbolAddress((void**)&AhoH, g_Aho_hi);
    cudaGetSymbolAddress((void**)&AhoL, g_Aho_lo);

    cudaFuncSetAttribute(mma_gemm<0, 256>, cudaFuncAttributeMaxDynamicSharedMemorySize, SMEM_BYTES);
    cudaFuncSetAttribute(mma_gemm<1, 256>, cudaFuncAttributeMaxDynamicSharedMemorySize, SMEM_BYTES);
    cudaFuncSetAttribute(mma_gemm<2, 768>, cudaFuncAttributeMaxDynamicSharedMemorySize, SMEM_BYTES);

    // 1. weights
    {
        int total = 3 * 65536 + 256 * 768;
        prep_k<<<(total + 255) / 256, 256>>>(w_o, w_p, w_k, lw, Whi, Wlo, Lhi, Llo);
    }
    // 2. input splits (hp, hk full; ho gathered)
    split_k<<<(N * 32 + 255) / 256, 256>>>(h_p, nullptr, AhpH, AhpL, N);
    split_k<<<(N * 32 + 255) / 256, 256>>>(h_k, nullptr, AhkH, AhkL, N);
    split_k<<<(M * 32 + 255) / 256, 256>>>(h_o, idxP, AhoH, AhoL, M);

    // 3. trans_hp / trans_hk GEMMs
    {
        dim3 grd((N + 127) / 128, 2);
        Args a = {};
        a.Ahi = AhpH; a.Alo = AhpL; a.Bhi = Whi + 1 * 65536; a.Blo = Wlo + 1 * 65536;
        a.outF = out; a.rowsC = N; a.Nfull = N;
        mma_gemm<0, 256><<<grd, 256, SMEM_BYTES>>>(a);
        Args b = {};
        b.Ahi = AhkH; b.Alo = AhkL; b.Bhi = Whi + 2 * 65536; b.Blo = Wlo + 2 * 65536;
        b.outF = out + (size_t)N * 256; b.rowsC = N; b.Nfull = N;
        mma_gemm<0, 256><<<grd, 256, SMEM_BYTES>>>(b);
    }
    // 4. gathered ho GEMM -> tanh -> T cols [0:256)
    {
        dim3 grd((M + 127) / 128, 2);
        Args a = {};
        a.Ahi = AhoH; a.Alo = AhoL; a.Bhi = Whi + 0 * 65536; a.Blo = Wlo + 0 * 65536;
        a.Thi = Thi; a.Tlo = Tlo; a.rowsC = M; a.Nfull = N;
        mma_gemm<1, 256><<<grd, 256, SMEM_BYTES>>>(a);
    }
    // 5. gather + tanh of trans rows -> T cols [256:768)
    gather_tanh_k<<<(M * 64 + 255) / 256, 256>>>(out, idxP, idxK, Thi, Tlo, M, N);
    // 6. final linear (K=768) + leaky + bias + scatter
    {
        dim3 grd((M + 127) / 128, 2);
        Args a = {};
        a.Ahi = Thi; a.Alo = Tlo; a.Bhi = Lhi; a.Blo = Llo;
        a.outF = out; a.idxP = idxP; a.idxK = idxK; a.lb = lb; a.bias = bs;
        a.rowsC = M; a.Nfull = N;
        mma_gemm<2, 768><<<grd, 256, SMEM_BYTES>>>(a);
    }
}

// round 6
// speedup vs baseline: 3.2412x; 1.4816x over previous
#include <cuda_runtime.h>
#include <cuda_fp16.h>
#include <math.h>
#include <stdint.h>

#define DDIM 256
#define NMAX 100000
#define MMAX 50000

// ---------------- device scratch (static; no runtime allocs) ---------------
__device__ __half g_Whi[3 * 256 * 256];   // transposed [n][k] hi
__device__ __half g_Wlo[3 * 256 * 256];   // transposed [n][k] lo
__device__ __half g_Lhi[256 * 768];       // linear_w [n][k]
__device__ __half g_Llo[256 * 768];
__device__ __half g_T[(size_t)MMAX * 768];  // tanh concat (fp16, A-side of final)

// ---------------- helpers --------------------------------------------------
__device__ __forceinline__ uint32_t smem_u32(const void* p) {
    uint32_t a;
    asm("{ .reg .u64 t; cvta.to.shared.u64 t, %1; cvt.u32.u64 %0, t; }" : "=r"(a) : "l"(p));
    return a;
}
__device__ __forceinline__ void ldmx4(uint32_t& r0, uint32_t& r1, uint32_t& r2, uint32_t& r3,
                                      uint32_t addr) {
    asm volatile("ldmatrix.sync.aligned.m8n8.x4.shared.b16 {%0,%1,%2,%3}, [%4];"
                 : "=r"(r0), "=r"(r1), "=r"(r2), "=r"(r3) : "r"(addr));
}
__device__ __forceinline__ void ldmx2(uint32_t& r0, uint32_t& r1, uint32_t addr) {
    asm volatile("ldmatrix.sync.aligned.m8n8.x2.shared.b16 {%0,%1}, [%2];"
                 : "=r"(r0), "=r"(r1) : "r"(addr));
}
__device__ __forceinline__ void mma16816(float* d, uint32_t a0, uint32_t a1, uint32_t a2,
                                         uint32_t a3, uint32_t b0, uint32_t b1) {
    asm volatile(
        "mma.sync.aligned.m16n8k16.row.col.f32.f16.f16.f32 "
        "{%0,%1,%2,%3}, {%4,%5,%6,%7}, {%8,%9}, {%0,%1,%2,%3};"
        : "+f"(d[0]), "+f"(d[1]), "+f"(d[2]), "+f"(d[3])
        : "r"(a0), "r"(a1), "r"(a2), "r"(a3), "r"(b0), "r"(b1));
}
#define SW128(o) ((o) ^ (((o) >> 3) & 0x70))

__device__ __forceinline__ void split_h(float x, __half& h, __half& l) {
    h = __float2half_rn(x);
    l = __float2half_rn(x - __half2float(h));
}

// smem: A[128][64] fp16 (16KB), Bhi[128][64] (16KB), Blo (16KB)
#define OFF_A   0
#define OFF_BHI 16384
#define OFF_BLO 32768
#define SMEM_BYTES 49152

struct Args {
    const float* Afp;          // MODE 0/1 A source (fp32)
    const __half* Ah;          // MODE 2 A source (fp16)
    const __half* Bhi;
    const __half* Blo;
    float* outF;
    __half* T;
    const int* rowmap;         // MODE 1 gather
    const int* idxP;
    const int* idxK;
    const float* lb;
    const float* bias;
    int rowsC;
    int Nfull;
};

// MODE: 0 = fp32 A, store fp32 rows; 1 = fp32 A gathered, tanh -> T fp16 cols [0:256);
//       2 = fp16 A (T), +lb, leaky, +bias, scatter to outF rows idxP / Nfull+idxK
template<int MODE, int KDIM>
__global__ void __launch_bounds__(256, 2)
mma_gemm(const Args args)
{
    extern __shared__ char smem[];
    const uint32_t sb = smem_u32(smem);
    const int tid = threadIdx.x;
    const int w = tid >> 5;
    const int lane = tid & 31;
    const int rowBase = blockIdx.x * 128;
    const int colBase = blockIdx.y * 128;
    const int rowsC = args.rowsC;

    const int wm = w & 1;         // 2 m-tiles of 64
    const int wn = w >> 1;        // 4 n-tiles of 32

    float acc[64];                // [mf][nf][4]
    #pragma unroll
    for (int i = 0; i < 64; i++) acc[i] = 0.0f;

    const int NCH = KDIM / 64;
    for (int c = 0; c < NCH; c++) {
        const int k0 = c * 64;
        // ---- fill A tile (128 rows x 64 k) fp16 ----
        #pragma unroll
        for (int i = 0; i < 4; i++) {
            int q = tid + i * 256;       // 0..1023
            int r = q >> 3;
            int j8 = (q & 7) * 8;
            uint32_t so = SW128((uint32_t)(r * 128 + j8 * 2));
            int gr = rowBase + r;
            if (MODE == 2) {
                uint4 v = make_uint4(0, 0, 0, 0);
                if (gr < rowsC) v = *(const uint4*)(args.Ah + (size_t)gr * KDIM + k0 + j8);
                *(uint4*)(smem + OFF_A + so) = v;
            } else {
                union { __half h[8]; uint4 u; } ua;
                if (gr < rowsC) {
                    int src = (MODE == 1) ? __ldg(args.rowmap + gr) : gr;
                    const float* ap = args.Afp + (size_t)src * 256 + k0 + j8;
                    float4 v0 = *(const float4*)ap;
                    float4 v1 = *(const float4*)(ap + 4);
                    ua.h[0] = __float2half_rn(v0.x); ua.h[1] = __float2half_rn(v0.y);
                    ua.h[2] = __float2half_rn(v0.z); ua.h[3] = __float2half_rn(v0.w);
                    ua.h[4] = __float2half_rn(v1.x); ua.h[5] = __float2half_rn(v1.y);
                    ua.h[6] = __float2half_rn(v1.z); ua.h[7] = __float2half_rn(v1.w);
                } else {
                    ua.u = make_uint4(0, 0, 0, 0);
                }
                *(uint4*)(smem + OFF_A + so) = ua.u;
            }
        }
        // ---- fill B tiles (128 n-rows x 64 k) hi/lo, stride KDIM ----
        #pragma unroll
        for (int i = 0; i < 4; i++) {
            int q = tid + i * 256;
            int n = q >> 3;
            int j8 = (q & 7) * 8;
            size_t off = (size_t)(colBase + n) * KDIM + k0 + j8;
            uint32_t so = SW128((uint32_t)(n * 128 + j8 * 2));
            *(uint4*)(smem + OFF_BHI + so) = *(const uint4*)(args.Bhi + off);
            *(uint4*)(smem + OFF_BLO + so) = *(const uint4*)(args.Blo + off);
        }
        __syncthreads();

        #pragma unroll
        for (int ks = 0; ks < 4; ks++) {
            uint32_t bh[4][2], bl[4][2];
            #pragma unroll
            for (int nf = 0; nf < 4; nf++) {
                int n = wn * 32 + nf * 8 + (lane & 7);
                uint32_t cby = (uint32_t)(ks * 32 + ((lane >> 3) & 1) * 16);
                uint32_t ad = sb + SW128((uint32_t)(n * 128) + cby);
                ldmx2(bh[nf][0], bh[nf][1], ad + OFF_BHI);
                ldmx2(bl[nf][0], bl[nf][1], ad + OFF_BLO);
            }
            #pragma unroll
            for (int mf = 0; mf < 4; mf++) {
                int m = wm * 64 + mf * 16 + (lane & 15);
                uint32_t cby = (uint32_t)(ks * 32 + (lane >> 4) * 16);
                uint32_t ad = sb + SW128((uint32_t)(m * 128) + cby);
                uint32_t a0, a1, a2, a3;
                ldmx4(a0, a1, a2, a3, ad + OFF_A);
                #pragma unroll
                for (int nf = 0; nf < 4; nf++) {
                    float* d = &acc[mf * 16 + nf * 4];
                    mma16816(d, a0, a1, a2, a3, bh[nf][0], bh[nf][1]);
                    mma16816(d, a0, a1, a2, a3, bl[nf][0], bl[nf][1]);
                }
            }
        }
        __syncthreads();
    }

    // ---- epilogue: thread covers (r,c),(r,c+1),(r+8,c),(r+8,c+1) per frag ----
    #pragma unroll
    for (int mf = 0; mf < 4; mf++) {
        int r0 = rowBase + wm * 64 + mf * 16 + (lane >> 2);
        #pragma unroll
        for (int half = 0; half < 2; half++) {
            int r = r0 + half * 8;
            if (r >= rowsC) continue;
            int pr = 0, kr = 0;
            if (MODE == 2) { pr = __ldg(args.idxP + r); kr = __ldg(args.idxK + r); }
            #pragma unroll
            for (int nf = 0; nf < 4; nf++) {
                int col = colBase + wn * 32 + nf * 8 + (lane & 3) * 2;
                float v0 = acc[mf * 16 + nf * 4 + half * 2 + 0];
                float v1 = acc[mf * 16 + nf * 4 + half * 2 + 1];
                if (MODE == 0) {
                    *(float2*)(args.outF + (size_t)r * 256 + col) = make_float2(v0, v1);
                } else if (MODE == 1) {
                    union { __half h[2]; uint32_t u; } t;
                    t.h[0] = __float2half_rn(tanhf(v0));
                    t.h[1] = __float2half_rn(tanhf(v1));
                    *(uint32_t*)(args.T + (size_t)r * 768 + col) = t.u;
                } else {
                    float x0 = v0 + __ldg(args.lb + col);
                    float x1 = v1 + __ldg(args.lb + col + 1);
                    x0 = (x0 > 0.0f) ? x0 : 0.01f * x0;
                    x1 = (x1 > 0.0f) ? x1 : 0.01f * x1;
                    x0 += __ldg(args.bias + col);
                    x1 += __ldg(args.bias + col + 1);
                    float2 v = make_float2(x0, x1);
                    *(float2*)(args.outF + (size_t)pr * 256 + col) = v;
                    *(float2*)(args.outF + (size_t)(args.Nfull + kr) * 256 + col) = v;
                }
            }
        }
    }
}

// ---------------------------------------------------------------------------
// prep: transpose+split 3 weights [k][n]->[n][k] hi/lo; split linear_w [n][k]
// ---------------------------------------------------------------------------
__global__ void prep_k(const float* __restrict__ wo, const float* __restrict__ wp,
                       const float* __restrict__ wk, const float* __restrict__ lw,
                       __half* __restrict__ Whi, __half* __restrict__ Wlo,
                       __half* __restrict__ Lhi, __half* __restrict__ Llo)
{
    int idx = blockIdx.x * blockDim.x + threadIdx.x;
    if (idx < 3 * 65536) {
        int wi = idx >> 16;
        int e = idx & 65535;
        int k = e >> 8, n = e & 255;
        const float* W = (wi == 0) ? wo : ((wi == 1) ? wp : wk);
        float v = W[k * 256 + n];
        __half h, l;
        split_h(v, h, l);
        Whi[wi * 65536 + n * 256 + k] = h;
        Wlo[wi * 65536 + n * 256 + k] = l;
    } else {
        int e = idx - 3 * 65536;
        if (e < 256 * 768) {
            __half h, l;
            split_h(lw[e], h, l);
            Lhi[e] = h;
            Llo[e] = l;
        }
    }
}

// ---------------------------------------------------------------------------
// gather trans_hp/trans_hk rows, tanh -> T fp16 cols [256:512),[512:768)
// ---------------------------------------------------------------------------
__global__ void gather_tanh_k(const float* __restrict__ out,
                              const int* __restrict__ idxP,
                              const int* __restrict__ idxK,
                              __half* __restrict__ T,
                              int Mr, int Nr)
{
    int idx = blockIdx.x * blockDim.x + threadIdx.x;   // M*64 work items
    int m = idx >> 6;
    int part = idx & 63;
    if (m >= Mr) return;
    const float* src;
    int dcol;
    if (part < 32) {
        int p = __ldg(idxP + m);
        src = out + (size_t)p * 256 + part * 8;
        dcol = 256 + part * 8;
    } else {
        int kq = __ldg(idxK + m);
        src = out + (size_t)Nr * 256 + (size_t)kq * 256 + (part - 32) * 8;
        dcol = 512 + (part - 32) * 8;
    }
    float4 v0 = *(const float4*)src;
    float4 v1 = *(const float4*)(src + 4);
    union { __half h[8]; uint4 u; } t;
    t.h[0] = __float2half_rn(tanhf(v0.x)); t.h[1] = __float2half_rn(tanhf(v0.y));
    t.h[2] = __float2half_rn(tanhf(v0.z)); t.h[3] = __float2half_rn(tanhf(v0.w));
    t.h[4] = __float2half_rn(tanhf(v1.x)); t.h[5] = __float2half_rn(tanhf(v1.y));
    t.h[6] = __float2half_rn(tanhf(v1.z)); t.h[7] = __float2half_rn(tanhf(v1.w));
    *(uint4*)(T + (size_t)m * 768 + dcol) = t.u;
}

extern "C" void kernel_launch(void* const* d_in, const int* in_sizes, int n_in,
                              void* d_out, int out_size)
{
    const float* h_p = (const float*)d_in[0];
    const float* h_k = (const float*)d_in[1];
    const float* h_o = (const float*)d_in[2];
    const int* idxP  = (const int*)d_in[3];
    const int* idxK  = (const int*)d_in[4];
    const float* w_o = (const float*)d_in[5];
    const float* w_p = (const float*)d_in[6];
    const float* w_k = (const float*)d_in[7];
    const float* lw  = (const float*)d_in[8];
    const float* lb  = (const float*)d_in[9];
    const float* bs  = (const float*)d_in[10];
    float* out = (float*)d_out;

    const int N = in_sizes[0] / DDIM;
    const int M = in_sizes[3];

    __half *Whi, *Wlo, *Lhi, *Llo, *T;
    cudaGetSymbolAddress((void**)&Whi, g_Whi);
    cudaGetSymbolAddress((void**)&Wlo, g_Wlo);
    cudaGetSymbolAddress((void**)&Lhi, g_Lhi);
    cudaGetSymbolAddress((void**)&Llo, g_Llo);
    cudaGetSymbolAddress((void**)&T, g_T);

    cudaFuncSetAttribute(mma_gemm<0, 256>, cudaFuncAttributeMaxDynamicSharedMemorySize, SMEM_BYTES);
    cudaFuncSetAttribute(mma_gemm<1, 256>, cudaFuncAttributeMaxDynamicSharedMemorySize, SMEM_BYTES);
    cudaFuncSetAttribute(mma_gemm<2, 768>, cudaFuncAttributeMaxDynamicSharedMemorySize, SMEM_BYTES);

    // 1. weights -> fp16 hi/lo (transposed)
    {
        int total = 3 * 65536 + 256 * 768;
        prep_k<<<(total + 255) / 256, 256>>>(w_o, w_p, w_k, lw, Whi, Wlo, Lhi, Llo);
    }
    // 2. trans_hp / trans_hk GEMMs (A converted on the fly)
    {
        dim3 grd((N + 127) / 128, 2);
        Args a = {};
        a.Afp = h_p; a.Bhi = Whi + 1 * 65536; a.Blo = Wlo + 1 * 65536;
        a.outF = out; a.rowsC = N; a.Nfull = N;
        mma_gemm<0, 256><<<grd, 256, SMEM_BYTES>>>(a);
        Args b = {};
        b.Afp = h_k; b.Bhi = Whi + 2 * 65536; b.Blo = Wlo + 2 * 65536;
        b.outF = out + (size_t)N * 256; b.rowsC = N; b.Nfull = N;
        mma_gemm<0, 256><<<grd, 256, SMEM_BYTES>>>(b);
    }
    // 3. gathered ho GEMM -> tanh -> T cols [0:256)
    {
        dim3 grd((M + 127) / 128, 2);
        Args a = {};
        a.Afp = h_o; a.Bhi = Whi + 0 * 65536; a.Blo = Wlo + 0 * 65536;
        a.T = T; a.rowmap = idxP; a.rowsC = M; a.Nfull = N;
        mma_gemm<1, 256><<<grd, 256, SMEM_BYTES>>>(a);
    }
    // 4. gather + tanh of trans rows -> T cols [256:768)
    gather_tanh_k<<<(M * 64 + 255) / 256, 256>>>(out, idxP, idxK, T, M, N);
    // 5. final linear (K=768) + leaky + bias + scatter
    {
        dim3 grd((M + 127) / 128, 2);
        Args a = {};
        a.Ah = T; a.Bhi = Lhi; a.Blo = Llo;
        a.outF = out; a.idxP = idxP; a.idxK = idxK; a.lb = lb; a.bias = bs;
        a.rowsC = M; a.Nfull = N;
        mma_gemm<2, 768><<<grd, 256, SMEM_BYTES>>>(a);
    }
}

// round 7
// speedup vs baseline: 3.6391x; 1.1228x over previous
#include <cuda_runtime.h>
#include <cuda_fp16.h>
#include <math.h>
#include <stdint.h>

#define DDIM 256
#define NMAX 100000
#define MMAX 50000

// ---------------- device scratch (static; no runtime allocs) ---------------
__device__ __half g_Whi[3 * 256 * 256];     // transposed [n][k] hi
__device__ __half g_Wlo[3 * 256 * 256];     // transposed [n][k] lo
__device__ __half g_Lhi[256 * 768];         // linear_w [n][k]
__device__ __half g_Llo[256 * 768];
__device__ __half g_T[(size_t)MMAX * 768];  // tanh concat (A of final GEMM)
__device__ __half g_Ahp[(size_t)NMAX * 256];
__device__ __half g_Ahk[(size_t)NMAX * 256];
__device__ __half g_Aho[(size_t)MMAX * 256];

// ---------------- helpers --------------------------------------------------
__device__ __forceinline__ uint32_t smem_u32(const void* p) {
    uint32_t a;
    asm("{ .reg .u64 t; cvta.to.shared.u64 t, %1; cvt.u32.u64 %0, t; }" : "=r"(a) : "l"(p));
    return a;
}
__device__ __forceinline__ void ldmx4(uint32_t& r0, uint32_t& r1, uint32_t& r2, uint32_t& r3,
                                      uint32_t addr) {
    asm volatile("ldmatrix.sync.aligned.m8n8.x4.shared.b16 {%0,%1,%2,%3}, [%4];"
                 : "=r"(r0), "=r"(r1), "=r"(r2), "=r"(r3) : "r"(addr));
}
__device__ __forceinline__ void ldmx2(uint32_t& r0, uint32_t& r1, uint32_t addr) {
    asm volatile("ldmatrix.sync.aligned.m8n8.x2.shared.b16 {%0,%1}, [%2];"
                 : "=r"(r0), "=r"(r1) : "r"(addr));
}
__device__ __forceinline__ void mma16816(float* d, uint32_t a0, uint32_t a1, uint32_t a2,
                                         uint32_t a3, uint32_t b0, uint32_t b1) {
    asm volatile(
        "mma.sync.aligned.m16n8k16.row.col.f32.f16.f16.f32 "
        "{%0,%1,%2,%3}, {%4,%5,%6,%7}, {%8,%9}, {%0,%1,%2,%3};"
        : "+f"(d[0]), "+f"(d[1]), "+f"(d[2]), "+f"(d[3])
        : "r"(a0), "r"(a1), "r"(a2), "r"(a3), "r"(b0), "r"(b1));
}
__device__ __forceinline__ void cp_async16(uint32_t dst, const void* src, bool pred) {
    int sz = pred ? 16 : 0;
    asm volatile("cp.async.cg.shared.global [%0], [%1], 16, %2;"
                 :: "r"(dst), "l"(src), "r"(sz));
}
#define CP_COMMIT()  asm volatile("cp.async.commit_group;" ::: "memory")
#define CP_WAIT(n)   asm volatile("cp.async.wait_group %0;" :: "n"(n) : "memory")
#define SW128(o) ((o) ^ (((o) >> 3) & 0x70))

__device__ __forceinline__ void split_h(float x, __half& h, __half& l) {
    h = __float2half_rn(x);
    l = __float2half_rn(x - __half2float(h));
}

// smem: 2 buffers of {A 16KB, Bhi 16KB, Blo 16KB}
#define BUF_STRIDE 49152
#define OFF_A   0
#define OFF_BHI 16384
#define OFF_BLO 32768
#define SMEM_BYTES (2 * BUF_STRIDE)

struct Args {
    const __half* Ah;
    const __half* Bhi;
    const __half* Blo;
    float* outF;
    __half* T;
    const int* idxP;
    const int* idxK;
    const float* lb;
    const float* bias;
    int rowsC;
    int Nfull;
};

// EPI: 0 = store fp32 rows; 1 = tanh -> T fp16 cols [0:256); 2 = +lb, leaky, +bias, scatter
template<int EPI, int KDIM>
__global__ void __launch_bounds__(256, 2)
mma_gemm(const Args args)
{
    extern __shared__ char smem[];
    const uint32_t sb = smem_u32(smem);
    const int tid = threadIdx.x;
    const int w = tid >> 5;
    const int lane = tid & 31;
    const int rowBase = blockIdx.x * 128;
    const int colBase = blockIdx.y * 128;
    const int rowsC = args.rowsC;

    const int wm = w & 1;
    const int wn = w >> 1;

    float acc[64];
    #pragma unroll
    for (int i = 0; i < 64; i++) acc[i] = 0.0f;

    // per-thread load geometry (16B granules; 8 threads per 64-fp16 row)
    const int lr = tid >> 3;            // 0..31 base row step 32
    const int lj8 = (tid & 7) * 8;      // k offset within chunk
    const uint32_t soA[4] = {
        SW128((uint32_t)((lr + 0) * 128 + lj8 * 2)),
        SW128((uint32_t)((lr + 32) * 128 + lj8 * 2)),
        SW128((uint32_t)((lr + 64) * 128 + lj8 * 2)),
        SW128((uint32_t)((lr + 96) * 128 + lj8 * 2))};

    const int NCH = KDIM / 64;

    auto issue_chunk = [&](int c) {
        const int k0 = c * 64;
        const uint32_t bufb = sb + (uint32_t)(c & 1) * BUF_STRIDE;
        #pragma unroll
        for (int i = 0; i < 4; i++) {
            int gr = rowBase + lr + i * 32;
            bool ok = (gr < rowsC);
            const __half* src = args.Ah + (size_t)(ok ? gr : 0) * KDIM + k0 + lj8;
            cp_async16(bufb + OFF_A + soA[i], src, ok);
        }
        #pragma unroll
        for (int i = 0; i < 4; i++) {
            int n = lr + i * 32;
            size_t off = (size_t)(colBase + n) * KDIM + k0 + lj8;
            cp_async16(bufb + OFF_BHI + soA[i], args.Bhi + off, true);
            cp_async16(bufb + OFF_BLO + soA[i], args.Blo + off, true);
        }
        CP_COMMIT();
    };

    issue_chunk(0);

    for (int c = 0; c < NCH; c++) {
        if (c + 1 < NCH) {
            issue_chunk(c + 1);
            CP_WAIT(1);
        } else {
            CP_WAIT(0);
        }
        __syncthreads();

        const uint32_t bufb = sb + (uint32_t)(c & 1) * BUF_STRIDE;
        #pragma unroll
        for (int ks = 0; ks < 4; ks++) {
            uint32_t bh[4][2], bl[4][2];
            #pragma unroll
            for (int nf = 0; nf < 4; nf++) {
                int n = wn * 32 + nf * 8 + (lane & 7);
                uint32_t cby = (uint32_t)(ks * 32 + ((lane >> 3) & 1) * 16);
                uint32_t ad = bufb + SW128((uint32_t)(n * 128) + cby);
                ldmx2(bh[nf][0], bh[nf][1], ad + OFF_BHI);
                ldmx2(bl[nf][0], bl[nf][1], ad + OFF_BLO);
            }
            #pragma unroll
            for (int mf = 0; mf < 4; mf++) {
                int m = wm * 64 + mf * 16 + (lane & 15);
                uint32_t cby = (uint32_t)(ks * 32 + (lane >> 4) * 16);
                uint32_t ad = bufb + SW128((uint32_t)(m * 128) + cby);
                uint32_t a0, a1, a2, a3;
                ldmx4(a0, a1, a2, a3, ad + OFF_A);
                #pragma unroll
                for (int nf = 0; nf < 4; nf++) {
                    float* d = &acc[mf * 16 + nf * 4];
                    mma16816(d, a0, a1, a2, a3, bh[nf][0], bh[nf][1]);
                    mma16816(d, a0, a1, a2, a3, bl[nf][0], bl[nf][1]);
                }
            }
        }
        __syncthreads();
    }

    // ---- epilogue ----
    #pragma unroll
    for (int mf = 0; mf < 4; mf++) {
        int r0 = rowBase + wm * 64 + mf * 16 + (lane >> 2);
        #pragma unroll
        for (int half = 0; half < 2; half++) {
            int r = r0 + half * 8;
            if (r >= rowsC) continue;
            int pr = 0, kr = 0;
            if (EPI == 2) { pr = __ldg(args.idxP + r); kr = __ldg(args.idxK + r); }
            #pragma unroll
            for (int nf = 0; nf < 4; nf++) {
                int col = colBase + wn * 32 + nf * 8 + (lane & 3) * 2;
                float v0 = acc[mf * 16 + nf * 4 + half * 2 + 0];
                float v1 = acc[mf * 16 + nf * 4 + half * 2 + 1];
                if (EPI == 0) {
                    *(float2*)(args.outF + (size_t)r * 256 + col) = make_float2(v0, v1);
                } else if (EPI == 1) {
                    union { __half h[2]; uint32_t u; } t;
                    t.h[0] = __float2half_rn(tanhf(v0));
                    t.h[1] = __float2half_rn(tanhf(v1));
                    *(uint32_t*)(args.T + (size_t)r * 768 + col) = t.u;
                } else {
                    float x0 = v0 + __ldg(args.lb + col);
                    float x1 = v1 + __ldg(args.lb + col + 1);
                    x0 = (x0 > 0.0f) ? x0 : 0.01f * x0;
                    x1 = (x1 > 0.0f) ? x1 : 0.01f * x1;
                    x0 += __ldg(args.bias + col);
                    x1 += __ldg(args.bias + col + 1);
                    float2 v = make_float2(x0, x1);
                    *(float2*)(args.outF + (size_t)pr * 256 + col) = v;
                    *(float2*)(args.outF + (size_t)(args.Nfull + kr) * 256 + col) = v;
                }
            }
        }
    }
}

// ---------------------------------------------------------------------------
__global__ void prep_k(const float* __restrict__ wo, const float* __restrict__ wp,
                       const float* __restrict__ wk, const float* __restrict__ lw,
                       __half* __restrict__ Whi, __half* __restrict__ Wlo,
                       __half* __restrict__ Lhi, __half* __restrict__ Llo)
{
    int idx = blockIdx.x * blockDim.x + threadIdx.x;
    if (idx < 3 * 65536) {
        int wi = idx >> 16;
        int e = idx & 65535;
        int k = e >> 8, n = e & 255;
        const float* W = (wi == 0) ? wo : ((wi == 1) ? wp : wk);
        float v = W[k * 256 + n];
        __half h, l;
        split_h(v, h, l);
        Whi[wi * 65536 + n * 256 + k] = h;
        Wlo[wi * 65536 + n * 256 + k] = l;
    } else {
        int e = idx - 3 * 65536;
        if (e < 256 * 768) {
            __half h, l;
            split_h(lw[e], h, l);
            Lhi[e] = h;
            Llo[e] = l;
        }
    }
}

// fp32 rows -> fp16 (optional gather)
__global__ void tohalf_k(const float* __restrict__ src, const int* __restrict__ rowmap,
                         __half* __restrict__ dst, int rows)
{
    int idx = blockIdx.x * blockDim.x + threadIdx.x;   // rows*32 items of 8
    int r = idx >> 5;
    int j8 = (idx & 31) * 8;
    if (r >= rows) return;
    int sr = rowmap ? __ldg(rowmap + r) : r;
    const float* ap = src + (size_t)sr * 256 + j8;
    float4 v0 = *(const float4*)ap;
    float4 v1 = *(const float4*)(ap + 4);
    union { __half h[8]; uint4 u; } t;
    t.h[0] = __float2half_rn(v0.x); t.h[1] = __float2half_rn(v0.y);
    t.h[2] = __float2half_rn(v0.z); t.h[3] = __float2half_rn(v0.w);
    t.h[4] = __float2half_rn(v1.x); t.h[5] = __float2half_rn(v1.y);
    t.h[6] = __float2half_rn(v1.z); t.h[7] = __float2half_rn(v1.w);
    *(uint4*)(dst + (size_t)r * 256 + j8) = t.u;
}

// gather trans rows, tanh -> T fp16 cols [256:512),[512:768)
__global__ void gather_tanh_k(const float* __restrict__ out,
                              const int* __restrict__ idxP,
                              const int* __restrict__ idxK,
                              __half* __restrict__ T,
                              int Mr, int Nr)
{
    int idx = blockIdx.x * blockDim.x + threadIdx.x;
    int m = idx >> 6;
    int part = idx & 63;
    if (m >= Mr) return;
    const float* src;
    int dcol;
    if (part < 32) {
        int p = __ldg(idxP + m);
        src = out + (size_t)p * 256 + part * 8;
        dcol = 256 + part * 8;
    } else {
        int kq = __ldg(idxK + m);
        src = out + (size_t)Nr * 256 + (size_t)kq * 256 + (part - 32) * 8;
        dcol = 512 + (part - 32) * 8;
    }
    float4 v0 = *(const float4*)src;
    float4 v1 = *(const float4*)(src + 4);
    union { __half h[8]; uint4 u; } t;
    t.h[0] = __float2half_rn(tanhf(v0.x)); t.h[1] = __float2half_rn(tanhf(v0.y));
    t.h[2] = __float2half_rn(tanhf(v0.z)); t.h[3] = __float2half_rn(tanhf(v0.w));
    t.h[4] = __float2half_rn(tanhf(v1.x)); t.h[5] = __float2half_rn(tanhf(v1.y));
    t.h[6] = __float2half_rn(tanhf(v1.z)); t.h[7] = __float2half_rn(tanhf(v1.w));
    *(uint4*)(T + (size_t)m * 768 + dcol) = t.u;
}

extern "C" void kernel_launch(void* const* d_in, const int* in_sizes, int n_in,
                              void* d_out, int out_size)
{
    const float* h_p = (const float*)d_in[0];
    const float* h_k = (const float*)d_in[1];
    const float* h_o = (const float*)d_in[2];
    const int* idxP  = (const int*)d_in[3];
    const int* idxK  = (const int*)d_in[4];
    const float* w_o = (const float*)d_in[5];
    const float* w_p = (const float*)d_in[6];
    const float* w_k = (const float*)d_in[7];
    const float* lw  = (const float*)d_in[8];
    const float* lb  = (const float*)d_in[9];
    const float* bs  = (const float*)d_in[10];
    float* out = (float*)d_out;

    const int N = in_sizes[0] / DDIM;
    const int M = in_sizes[3];

    __half *Whi, *Wlo, *Lhi, *Llo, *T, *Ahp, *Ahk, *Aho;
    cudaGetSymbolAddress((void**)&Whi, g_Whi);
    cudaGetSymbolAddress((void**)&Wlo, g_Wlo);
    cudaGetSymbolAddress((void**)&Lhi, g_Lhi);
    cudaGetSymbolAddress((void**)&Llo, g_Llo);
    cudaGetSymbolAddress((void**)&T, g_T);
    cudaGetSymbolAddress((void**)&Ahp, g_Ahp);
    cudaGetSymbolAddress((void**)&Ahk, g_Ahk);
    cudaGetSymbolAddress((void**)&Aho, g_Aho);

    cudaFuncSetAttribute(mma_gemm<0, 256>, cudaFuncAttributeMaxDynamicSharedMemorySize, SMEM_BYTES);
    cudaFuncSetAttribute(mma_gemm<1, 256>, cudaFuncAttributeMaxDynamicSharedMemorySize, SMEM_BYTES);
    cudaFuncSetAttribute(mma_gemm<2, 768>, cudaFuncAttributeMaxDynamicSharedMemorySize, SMEM_BYTES);

    // 1. weights -> fp16 hi/lo (transposed); inputs -> fp16
    {
        int total = 3 * 65536 + 256 * 768;
        prep_k<<<(total + 255) / 256, 256>>>(w_o, w_p, w_k, lw, Whi, Wlo, Lhi, Llo);
    }
    tohalf_k<<<(N * 32 + 255) / 256, 256>>>(h_p, nullptr, Ahp, N);
    tohalf_k<<<(N * 32 + 255) / 256, 256>>>(h_k, nullptr, Ahk, N);
    tohalf_k<<<(M * 32 + 255) / 256, 256>>>(h_o, idxP, Aho, M);

    // 2. trans_hp / trans_hk GEMMs
    {
        dim3 grd((N + 127) / 128, 2);
        Args a = {};
        a.Ah = Ahp; a.Bhi = Whi + 1 * 65536; a.Blo = Wlo + 1 * 65536;
        a.outF = out; a.rowsC = N; a.Nfull = N;
        mma_gemm<0, 256><<<grd, 256, SMEM_BYTES>>>(a);
        Args b = {};
        b.Ah = Ahk; b.Bhi = Whi + 2 * 65536; b.Blo = Wlo + 2 * 65536;
        b.outF = out + (size_t)N * 256; b.rowsC = N; b.Nfull = N;
        mma_gemm<0, 256><<<grd, 256, SMEM_BYTES>>>(b);
    }
    // 3. gathered ho GEMM -> tanh -> T cols [0:256)
    {
        dim3 grd((M + 127) / 128, 2);
        Args a = {};
        a.Ah = Aho; a.Bhi = Whi + 0 * 65536; a.Blo = Wlo + 0 * 65536;
        a.T = T; a.rowsC = M; a.Nfull = N;
        mma_gemm<1, 256><<<grd, 256, SMEM_BYTES>>>(a);
    }
    // 4. gather + tanh of trans rows -> T cols [256:768)
    gather_tanh_k<<<(M * 64 + 255) / 256, 256>>>(out, idxP, idxK, T, M, N);
    // 5. final linear (K=768) + leaky + bias + scatter
    {
        dim3 grd((M + 127) / 128, 2);
        Args a = {};
        a.Ah = T; a.Bhi = Lhi; a.Blo = Llo;
        a.outF = out; a.idxP = idxP; a.idxK = idxK; a.lb = lb; a.bias = bs;
        a.rowsC = M; a.Nfull = N;
        mma_gemm<2, 768><<<grd, 256, SMEM_BYTES>>>(a);
    }
}

// round 8
// speedup vs baseline: 3.6752x; 1.0099x over previous
#include <cuda_runtime.h>
#include <cuda_fp16.h>
#include <math.h>
#include <stdint.h>

#define DDIM 256
#define NMAX 100000
#define MMAX 50000

// ---------------- device scratch (static; no runtime allocs) ---------------
__device__ __half g_Whi[3 * 256 * 256];     // transposed [n][k] hi
__device__ __half g_Wlo[3 * 256 * 256];     // transposed [n][k] lo
__device__ __half g_Lhi[256 * 768];         // linear_w [n][k]
__device__ __half g_Llo[256 * 768];
__device__ __half g_T[(size_t)MMAX * 768];  // tanh concat (A of final GEMM)
__device__ __half g_Ahp[(size_t)NMAX * 256];
__device__ __half g_Ahk[(size_t)NMAX * 256];
__device__ __half g_Aho[(size_t)MMAX * 256];

// ---------------- helpers --------------------------------------------------
__device__ __forceinline__ uint32_t smem_u32(const void* p) {
    uint32_t a;
    asm("{ .reg .u64 t; cvta.to.shared.u64 t, %1; cvt.u32.u64 %0, t; }" : "=r"(a) : "l"(p));
    return a;
}
__device__ __forceinline__ void ldmx4(uint32_t& r0, uint32_t& r1, uint32_t& r2, uint32_t& r3,
                                      uint32_t addr) {
    asm volatile("ldmatrix.sync.aligned.m8n8.x4.shared.b16 {%0,%1,%2,%3}, [%4];"
                 : "=r"(r0), "=r"(r1), "=r"(r2), "=r"(r3) : "r"(addr));
}
__device__ __forceinline__ void mma16816(float* d, uint32_t a0, uint32_t a1, uint32_t a2,
                                         uint32_t a3, uint32_t b0, uint32_t b1) {
    asm volatile(
        "mma.sync.aligned.m16n8k16.row.col.f32.f16.f16.f32 "
        "{%0,%1,%2,%3}, {%4,%5,%6,%7}, {%8,%9}, {%0,%1,%2,%3};"
        : "+f"(d[0]), "+f"(d[1]), "+f"(d[2]), "+f"(d[3])
        : "r"(a0), "r"(a1), "r"(a2), "r"(a3), "r"(b0), "r"(b1));
}
__device__ __forceinline__ void cp_async16(uint32_t dst, const void* src, bool pred) {
    int sz = pred ? 16 : 0;
    asm volatile("cp.async.cg.shared.global [%0], [%1], 16, %2;"
                 :: "r"(dst), "l"(src), "r"(sz));
}
#define CP_COMMIT()  asm volatile("cp.async.commit_group;" ::: "memory")
#define CP_WAIT_ALL() asm volatile("cp.async.wait_group 0;" ::: "memory")
#define SW128(o) ((o) ^ (((o) >> 3) & 0x70))

__device__ __forceinline__ void split_h(float x, __half& h, __half& l) {
    h = __float2half_rn(x);
    l = __float2half_rn(x - __half2float(h));
}

// smem: 2 buffers of {A 16KB, Bhi 16KB, Blo 16KB}
#define BUF_STRIDE 49152
#define OFF_A   0
#define OFF_BHI 16384
#define OFF_BLO 32768
#define SMEM_BYTES (2 * BUF_STRIDE)

struct Args {
    const __half* Ah;
    const __half* Bhi;
    const __half* Blo;
    float* outF;
    __half* T;
    const int* idxP;
    const int* idxK;
    const float* lb;
    const float* bias;
    int rowsC;
    int Nfull;
};

// EPI: 0 = store fp32 rows; 1 = tanh -> T fp16 cols [0:256); 2 = +lb, leaky, +bias, scatter
template<int EPI, int KDIM>
__global__ void __launch_bounds__(256, 2)
mma_gemm(const Args args)
{
    extern __shared__ char smem[];
    const uint32_t sb = smem_u32(smem);
    const int tid = threadIdx.x;
    const int w = tid >> 5;
    const int lane = tid & 31;
    const int rowBase = blockIdx.x * 128;
    const int colBase = blockIdx.y * 128;
    const int rowsC = args.rowsC;

    const int wm = w & 1;
    const int wn = w >> 1;

    float acc[64];
    #pragma unroll
    for (int i = 0; i < 64; i++) acc[i] = 0.0f;

    // per-thread load geometry (16B granules; 8 threads per 64-fp16 row)
    const int lr = tid >> 3;            // 0..31, row step 32
    const int lj8 = (tid & 7) * 8;      // k offset within chunk
    const uint32_t soA[4] = {
        SW128((uint32_t)((lr + 0) * 128 + lj8 * 2)),
        SW128((uint32_t)((lr + 32) * 128 + lj8 * 2)),
        SW128((uint32_t)((lr + 64) * 128 + lj8 * 2)),
        SW128((uint32_t)((lr + 96) * 128 + lj8 * 2))};

    const int NCH = KDIM / 64;

    auto issue_chunk = [&](int c) {
        const int k0 = c * 64;
        const uint32_t bufb = sb + (uint32_t)(c & 1) * BUF_STRIDE;
        #pragma unroll
        for (int i = 0; i < 4; i++) {
            int gr = rowBase + lr + i * 32;
            bool ok = (gr < rowsC);
            const __half* src = args.Ah + (size_t)(ok ? gr : 0) * KDIM + k0 + lj8;
            cp_async16(bufb + OFF_A + soA[i], src, ok);
        }
        #pragma unroll
        for (int i = 0; i < 4; i++) {
            int n = lr + i * 32;
            size_t off = (size_t)(colBase + n) * KDIM + k0 + lj8;
            cp_async16(bufb + OFF_BHI + soA[i], args.Bhi + off, true);
            cp_async16(bufb + OFF_BLO + soA[i], args.Blo + off, true);
        }
        CP_COMMIT();
    };

    // ldmatrix address precompute (per-thread, chunk-invariant parts)
    // B combined hi/lo x4: lanes 0-15 -> Bhi, lanes 16-31 -> Blo
    const int bgrp = lane >> 4;                 // 0 = hi, 1 = lo
    const int bwithin = lane & 15;
    const int bnrow = wn * 32 + (bwithin & 7);  // + nf*8
    const uint32_t bcol16 = (uint32_t)(((bwithin >> 3) & 1) * 16);
    const uint32_t boff = bgrp ? OFF_BLO : OFF_BHI;
    // A x4: lanes 0-15 rows m..m+15 col ks*32, lanes 16-31 same rows col +16
    const int amrow = wm * 64 + (lane & 15);    // + mf*16
    const uint32_t acol16 = (uint32_t)((lane >> 4) * 16);

    issue_chunk(0);

    for (int c = 0; c < NCH; c++) {
        CP_WAIT_ALL();
        __syncthreads();
        if (c + 1 < NCH) issue_chunk(c + 1);

        const uint32_t bufb = sb + (uint32_t)(c & 1) * BUF_STRIDE;
        #pragma unroll
        for (int ks = 0; ks < 4; ks++) {
            uint32_t bh[4][2], bl[4][2];
            #pragma unroll
            for (int nf = 0; nf < 4; nf++) {
                uint32_t ad = bufb + boff +
                    SW128((uint32_t)((bnrow + nf * 8) * 128) + (uint32_t)(ks * 32) + bcol16);
                ldmx4(bh[nf][0], bh[nf][1], bl[nf][0], bl[nf][1], ad);
            }
            #pragma unroll
            for (int mf = 0; mf < 4; mf++) {
                uint32_t ad = bufb + OFF_A +
                    SW128((uint32_t)((amrow + mf * 16) * 128) + (uint32_t)(ks * 32) + acol16);
                uint32_t a0, a1, a2, a3;
                ldmx4(a0, a1, a2, a3, ad);
                #pragma unroll
                for (int nf = 0; nf < 4; nf++) {
                    float* d = &acc[mf * 16 + nf * 4];
                    mma16816(d, a0, a1, a2, a3, bh[nf][0], bh[nf][1]);
                    mma16816(d, a0, a1, a2, a3, bl[nf][0], bl[nf][1]);
                }
            }
        }
        // no second barrier: buffer (c+1)&1 was last read in chunk c-1,
        // and every warp passed the top barrier of chunk c after that.
    }

    // ---- epilogue ----
    #pragma unroll
    for (int mf = 0; mf < 4; mf++) {
        int r0 = rowBase + wm * 64 + mf * 16 + (lane >> 2);
        #pragma unroll
        for (int half = 0; half < 2; half++) {
            int r = r0 + half * 8;
            if (r >= rowsC) continue;
            int pr = 0, kr = 0;
            if (EPI == 2) { pr = __ldg(args.idxP + r); kr = __ldg(args.idxK + r); }
            #pragma unroll
            for (int nf = 0; nf < 4; nf++) {
                int col = colBase + wn * 32 + nf * 8 + (lane & 3) * 2;
                float v0 = acc[mf * 16 + nf * 4 + half * 2 + 0];
                float v1 = acc[mf * 16 + nf * 4 + half * 2 + 1];
                if (EPI == 0) {
                    *(float2*)(args.outF + (size_t)r * 256 + col) = make_float2(v0, v1);
                } else if (EPI == 1) {
                    union { __half h[2]; uint32_t u; } t;
                    t.h[0] = __float2half_rn(tanhf(v0));
                    t.h[1] = __float2half_rn(tanhf(v1));
                    *(uint32_t*)(args.T + (size_t)r * 768 + col) = t.u;
                } else {
                    float x0 = v0 + __ldg(args.lb + col);
                    float x1 = v1 + __ldg(args.lb + col + 1);
                    x0 = (x0 > 0.0f) ? x0 : 0.01f * x0;
                    x1 = (x1 > 0.0f) ? x1 : 0.01f * x1;
                    x0 += __ldg(args.bias + col);
                    x1 += __ldg(args.bias + col + 1);
                    float2 v = make_float2(x0, x1);
                    *(float2*)(args.outF + (size_t)pr * 256 + col) = v;
                    *(float2*)(args.outF + (size_t)(args.Nfull + kr) * 256 + col) = v;
                }
            }
        }
    }
}

// ---------------------------------------------------------------------------
// prep_all: one launch does weights (transpose+split) and all input fp16 casts
//   region 0: 3*65536 weight elems        (1 elem/thread)
//   region 1: 256*768 linear_w elems      (1 elem/thread)
//   region 2: N*32 hp granules of 8       region 3: N*32 hk    region 4: M*32 ho
// ---------------------------------------------------------------------------
__global__ void prep_all(const float* __restrict__ wo, const float* __restrict__ wp,
                         const float* __restrict__ wk, const float* __restrict__ lw,
                         const float* __restrict__ hp, const float* __restrict__ hk,
                         const float* __restrict__ ho, const int* __restrict__ idxP,
                         __half* __restrict__ Whi, __half* __restrict__ Wlo,
                         __half* __restrict__ Lhi, __half* __restrict__ Llo,
                         __half* __restrict__ Ahp, __half* __restrict__ Ahk,
                         __half* __restrict__ Aho, int N, int M)
{
    int idx = blockIdx.x * blockDim.x + threadIdx.x;
    const int R0 = 3 * 65536;
    const int R1 = R0 + 256 * 768;
    const int R2 = R1 + N * 32;
    const int R3 = R2 + N * 32;
    const int R4 = R3 + M * 32;
    if (idx < R0) {
        int wi = idx >> 16;
        int e = idx & 65535;
        int k = e >> 8, n = e & 255;
        const float* W = (wi == 0) ? wo : ((wi == 1) ? wp : wk);
        float v = W[k * 256 + n];
        __half h, l;
        split_h(v, h, l);
        Whi[wi * 65536 + n * 256 + k] = h;
        Wlo[wi * 65536 + n * 256 + k] = l;
    } else if (idx < R1) {
        int e = idx - R0;
        __half h, l;
        split_h(lw[e], h, l);
        Lhi[e] = h;
        Llo[e] = l;
    } else if (idx < R4) {
        const float* src;
        __half* dst;
        int r, j8;
        if (idx < R2) {
            int e = idx - R1; r = e >> 5; j8 = (e & 31) * 8; src = hp + (size_t)r * 256 + j8; dst = Ahp;
        } else if (idx < R3) {
            int e = idx - R2; r = e >> 5; j8 = (e & 31) * 8; src = hk + (size_t)r * 256 + j8; dst = Ahk;
        } else {
            int e = idx - R3; r = e >> 5; j8 = (e & 31) * 8;
            src = ho + (size_t)__ldg(idxP + r) * 256 + j8; dst = Aho;
        }
        float4 v0 = *(const float4*)src;
        float4 v1 = *(const float4*)(src + 4);
        union { __half h[8]; uint4 u; } t;
        t.h[0] = __float2half_rn(v0.x); t.h[1] = __float2half_rn(v0.y);
        t.h[2] = __float2half_rn(v0.z); t.h[3] = __float2half_rn(v0.w);
        t.h[4] = __float2half_rn(v1.x); t.h[5] = __float2half_rn(v1.y);
        t.h[6] = __float2half_rn(v1.z); t.h[7] = __float2half_rn(v1.w);
        *(uint4*)(dst + (size_t)r * 256 + j8) = t.u;
    }
}

// gather trans rows, tanh -> T fp16 cols [256:512),[512:768)
__global__ void gather_tanh_k(const float* __restrict__ out,
                              const int* __restrict__ idxP,
                              const int* __restrict__ idxK,
                              __half* __restrict__ T,
                              int Mr, int Nr)
{
    int idx = blockIdx.x * blockDim.x + threadIdx.x;
    int m = idx >> 6;
    int part = idx & 63;
    if (m >= Mr) return;
    const float* src;
    int dcol;
    if (part < 32) {
        int p = __ldg(idxP + m);
        src = out + (size_t)p * 256 + part * 8;
        dcol = 256 + part * 8;
    } else {
        int kq = __ldg(idxK + m);
        src = out + (size_t)Nr * 256 + (size_t)kq * 256 + (part - 32) * 8;
        dcol = 512 + (part - 32) * 8;
    }
    float4 v0 = *(const float4*)src;
    float4 v1 = *(const float4*)(src + 4);
    union { __half h[8]; uint4 u; } t;
    t.h[0] = __float2half_rn(tanhf(v0.x)); t.h[1] = __float2half_rn(tanhf(v0.y));
    t.h[2] = __float2half_rn(tanhf(v0.z)); t.h[3] = __float2half_rn(tanhf(v0.w));
    t.h[4] = __float2half_rn(tanhf(v1.x)); t.h[5] = __float2half_rn(tanhf(v1.y));
    t.h[6] = __float2half_rn(tanhf(v1.z)); t.h[7] = __float2half_rn(tanhf(v1.w));
    *(uint4*)(T + (size_t)m * 768 + dcol) = t.u;
}

extern "C" void kernel_launch(void* const* d_in, const int* in_sizes, int n_in,
                              void* d_out, int out_size)
{
    const float* h_p = (const float*)d_in[0];
    const float* h_k = (const float*)d_in[1];
    const float* h_o = (const float*)d_in[2];
    const int* idxP  = (const int*)d_in[3];
    const int* idxK  = (const int*)d_in[4];
    const float* w_o = (const float*)d_in[5];
    const float* w_p = (const float*)d_in[6];
    const float* w_k = (const float*)d_in[7];
    const float* lw  = (const float*)d_in[8];
    const float* lb  = (const float*)d_in[9];
    const float* bs  = (const float*)d_in[10];
    float* out = (float*)d_out;

    const int N = in_sizes[0] / DDIM;
    const int M = in_sizes[3];

    __half *Whi, *Wlo, *Lhi, *Llo, *T, *Ahp, *Ahk, *Aho;
    cudaGetSymbolAddress((void**)&Whi, g_Whi);
    cudaGetSymbolAddress((void**)&Wlo, g_Wlo);
    cudaGetSymbolAddress((void**)&Lhi, g_Lhi);
    cudaGetSymbolAddress((void**)&Llo, g_Llo);
    cudaGetSymbolAddress((void**)&T, g_T);
    cudaGetSymbolAddress((void**)&Ahp, g_Ahp);
    cudaGetSymbolAddress((void**)&Ahk, g_Ahk);
    cudaGetSymbolAddress((void**)&Aho, g_Aho);

    cudaFuncSetAttribute(mma_gemm<0, 256>, cudaFuncAttributeMaxDynamicSharedMemorySize, SMEM_BYTES);
    cudaFuncSetAttribute(mma_gemm<1, 256>, cudaFuncAttributeMaxDynamicSharedMemorySize, SMEM_BYTES);
    cudaFuncSetAttribute(mma_gemm<2, 768>, cudaFuncAttributeMaxDynamicSharedMemorySize, SMEM_BYTES);

    // 1. all prep in one launch
    {
        int total = 3 * 65536 + 256 * 768 + N * 32 + N * 32 + M * 32;
        prep_all<<<(total + 255) / 256, 256>>>(w_o, w_p, w_k, lw, h_p, h_k, h_o, idxP,
                                               Whi, Wlo, Lhi, Llo, Ahp, Ahk, Aho, N, M);
    }
    // 2. trans_hp / trans_hk GEMMs
    {
        dim3 grd((N + 127) / 128, 2);
        Args a = {};
        a.Ah = Ahp; a.Bhi = Whi + 1 * 65536; a.Blo = Wlo + 1 * 65536;
        a.outF = out; a.rowsC = N; a.Nfull = N;
        mma_gemm<0, 256><<<grd, 256, SMEM_BYTES>>>(a);
        Args b = {};
        b.Ah = Ahk; b.Bhi = Whi + 2 * 65536; b.Blo = Wlo + 2 * 65536;
        b.outF = out + (size_t)N * 256; b.rowsC = N; b.Nfull = N;
        mma_gemm<0, 256><<<grd, 256, SMEM_BYTES>>>(b);
    }
    // 3. gathered ho GEMM -> tanh -> T cols [0:256)
    {
        dim3 grd((M + 127) / 128, 2);
        Args a = {};
        a.Ah = Aho; a.Bhi = Whi + 0 * 65536; a.Blo = Wlo + 0 * 65536;
        a.T = T; a.rowsC = M; a.Nfull = N;
        mma_gemm<1, 256><<<grd, 256, SMEM_BYTES>>>(a);
    }
    // 4. gather + tanh of trans rows -> T cols [256:768)
    gather_tanh_k<<<(M * 64 + 255) / 256, 256>>>(out, idxP, idxK, T, M, N);
    // 5. final linear (K=768) + leaky + bias + scatter
    {
        dim3 grd((M + 127) / 128, 2);
        Args a = {};
        a.Ah = T; a.Bhi = Lhi; a.Blo = Llo;
        a.outF = out; a.idxP = idxP; a.idxK = idxK; a.lb = lb; a.bias = bs;
        a.rowsC = M; a.Nfull = N;
        mma_gemm<2, 768><<<grd, 256, SMEM_BYTES>>>(a);
    }
}

// round 9
// speedup vs baseline: 3.7457x; 1.0192x over previous
#include <cuda_runtime.h>
#include <cuda_fp16.h>
#include <math.h>
#include <stdint.h>

#define DDIM 256
#define NMAX 100000
#define MMAX 50000

// ---------------- device scratch (static; no runtime allocs) ---------------
__device__ __half g_Whi[3 * 256 * 256];     // transposed [n][k] hi
__device__ __half g_Wlo[3 * 256 * 256];     // transposed [n][k] lo
__device__ __half g_Lhi[256 * 768];         // linear_w [n][k]
__device__ __half g_Llo[256 * 768];
__device__ __half g_T[(size_t)MMAX * 768];  // tanh concat (A of final GEMM)
__device__ __half g_Ahp[(size_t)NMAX * 256];
__device__ __half g_Ahk[(size_t)NMAX * 256];
__device__ __half g_Aho[(size_t)MMAX * 256];

// ---------------- helpers --------------------------------------------------
__device__ __forceinline__ uint32_t smem_u32(const void* p) {
    uint32_t a;
    asm("{ .reg .u64 t; cvta.to.shared.u64 t, %1; cvt.u32.u64 %0, t; }" : "=r"(a) : "l"(p));
    return a;
}
__device__ __forceinline__ void ldmx4(uint32_t& r0, uint32_t& r1, uint32_t& r2, uint32_t& r3,
                                      uint32_t addr) {
    asm volatile("ldmatrix.sync.aligned.m8n8.x4.shared.b16 {%0,%1,%2,%3}, [%4];"
                 : "=r"(r0), "=r"(r1), "=r"(r2), "=r"(r3) : "r"(addr));
}
__device__ __forceinline__ void mma16816(float* d, uint32_t a0, uint32_t a1, uint32_t a2,
                                         uint32_t a3, uint32_t b0, uint32_t b1) {
    asm volatile(
        "mma.sync.aligned.m16n8k16.row.col.f32.f16.f16.f32 "
        "{%0,%1,%2,%3}, {%4,%5,%6,%7}, {%8,%9}, {%0,%1,%2,%3};"
        : "+f"(d[0]), "+f"(d[1]), "+f"(d[2]), "+f"(d[3])
        : "r"(a0), "r"(a1), "r"(a2), "r"(a3), "r"(b0), "r"(b1));
}
__device__ __forceinline__ void cp_async16(uint32_t dst, const void* src, bool pred) {
    int sz = pred ? 16 : 0;
    asm volatile("cp.async.cg.shared.global [%0], [%1], 16, %2;"
                 :: "r"(dst), "l"(src), "r"(sz));
}
#define CP_COMMIT()  asm volatile("cp.async.commit_group;" ::: "memory")
#define CP_WAIT_ALL() asm volatile("cp.async.wait_group 0;" ::: "memory")
#define SW128(o) ((o) ^ (((o) >> 3) & 0x70))

__device__ __forceinline__ void split_h(float x, __half& h, __half& l) {
    h = __float2half_rn(x);
    l = __float2half_rn(x - __half2float(h));
}

// smem: 2 buffers of {A 16KB, Bhi 16KB, Blo 16KB}
#define BUF_STRIDE 49152
#define OFF_A   0
#define OFF_BHI 16384
#define OFF_BLO 32768
#define SMEM_BYTES (2 * BUF_STRIDE)

struct Args {
    const __half* Ah;
    const __half* Bhi;
    const __half* Blo;
    float* outF;
    __half* T;
    const int* idxP;
    const int* idxK;
    const float* lb;
    const float* bias;
    int rowsC;
    int Nfull;
};

// EPI: 0 = store fp32 rows; 1 = tanh -> T fp16 cols [0:256); 2 = +lb, leaky, +bias, scatter
template<int EPI, int KDIM>
__global__ void __launch_bounds__(256, 2)
mma_gemm(const Args args)
{
    extern __shared__ char smem[];
    const uint32_t sb = smem_u32(smem);
    const int tid = threadIdx.x;
    const int w = tid >> 5;
    const int lane = tid & 31;
    const int rowBase = blockIdx.x * 128;
    const int colBase = blockIdx.y * 128;
    const int rowsC = args.rowsC;

    const int wm = w & 1;
    const int wn = w >> 1;

    float acc[64];
    #pragma unroll
    for (int i = 0; i < 64; i++) acc[i] = 0.0f;

    // per-thread load geometry (16B granules; 8 threads per 64-fp16 row)
    const int lr = tid >> 3;            // 0..31, row step 32
    const int lj8 = (tid & 7) * 8;      // k offset within chunk
    const uint32_t soA[4] = {
        SW128((uint32_t)((lr + 0) * 128 + lj8 * 2)),
        SW128((uint32_t)((lr + 32) * 128 + lj8 * 2)),
        SW128((uint32_t)((lr + 64) * 128 + lj8 * 2)),
        SW128((uint32_t)((lr + 96) * 128 + lj8 * 2))};

    const int NCH = KDIM / 64;

    auto issue_chunk = [&](int c) {
        const int k0 = c * 64;
        const uint32_t bufb = sb + (uint32_t)(c & 1) * BUF_STRIDE;
        #pragma unroll
        for (int i = 0; i < 4; i++) {
            int gr = rowBase + lr + i * 32;
            bool ok = (gr < rowsC);
            const __half* src = args.Ah + (size_t)(ok ? gr : 0) * KDIM + k0 + lj8;
            cp_async16(bufb + OFF_A + soA[i], src, ok);
        }
        #pragma unroll
        for (int i = 0; i < 4; i++) {
            int n = lr + i * 32;
            size_t off = (size_t)(colBase + n) * KDIM + k0 + lj8;
            cp_async16(bufb + OFF_BHI + soA[i], args.Bhi + off, true);
            cp_async16(bufb + OFF_BLO + soA[i], args.Blo + off, true);
        }
        CP_COMMIT();
    };

    // ldmatrix address precompute
    // B combined hi/lo x4: lanes 0-15 -> Bhi, lanes 16-31 -> Blo
    const int bgrp = lane >> 4;
    const int bwithin = lane & 15;
    const int bnrow = wn * 32 + (bwithin & 7);
    const uint32_t bcol16 = (uint32_t)(((bwithin >> 3) & 1) * 16);
    const uint32_t boff = bgrp ? OFF_BLO : OFF_BHI;
    // A x4: lanes 0-15 rows m..m+15 col ks*32, lanes 16-31 same rows col +16
    const int amrow = wm * 64 + (lane & 15);
    const uint32_t acol16 = (uint32_t)((lane >> 4) * 16);

    issue_chunk(0);

    for (int c = 0; c < NCH; c++) {
        CP_WAIT_ALL();
        __syncthreads();
        if (c + 1 < NCH) issue_chunk(c + 1);

        const uint32_t bufb = sb + (uint32_t)(c & 1) * BUF_STRIDE;
        #pragma unroll
        for (int ks = 0; ks < 4; ks++) {
            // ---- hoist ALL fragment loads for this ks ----
            uint32_t bh[4][2], bl[4][2];
            uint32_t a[4][4];
            #pragma unroll
            for (int nf = 0; nf < 4; nf++) {
                uint32_t ad = bufb + boff +
                    SW128((uint32_t)((bnrow + nf * 8) * 128) + (uint32_t)(ks * 32) + bcol16);
                ldmx4(bh[nf][0], bh[nf][1], bl[nf][0], bl[nf][1], ad);
            }
            #pragma unroll
            for (int mf = 0; mf < 4; mf++) {
                uint32_t ad = bufb + OFF_A +
                    SW128((uint32_t)((amrow + mf * 16) * 128) + (uint32_t)(ks * 32) + acol16);
                ldmx4(a[mf][0], a[mf][1], a[mf][2], a[mf][3], ad);
            }
            // ---- hi sweep: 16 independent MMAs (RAW distance 16) ----
            #pragma unroll
            for (int mf = 0; mf < 4; mf++)
                #pragma unroll
                for (int nf = 0; nf < 4; nf++)
                    mma16816(&acc[mf * 16 + nf * 4],
                             a[mf][0], a[mf][1], a[mf][2], a[mf][3],
                             bh[nf][0], bh[nf][1]);
            // ---- lo sweep ----
            #pragma unroll
            for (int mf = 0; mf < 4; mf++)
                #pragma unroll
                for (int nf = 0; nf < 4; nf++)
                    mma16816(&acc[mf * 16 + nf * 4],
                             a[mf][0], a[mf][1], a[mf][2], a[mf][3],
                             bl[nf][0], bl[nf][1]);
        }
    }

    // ---- epilogue ----
    #pragma unroll
    for (int mf = 0; mf < 4; mf++) {
        int r0 = rowBase + wm * 64 + mf * 16 + (lane >> 2);
        #pragma unroll
        for (int half = 0; half < 2; half++) {
            int r = r0 + half * 8;
            if (r >= rowsC) continue;
            int pr = 0, kr = 0;
            if (EPI == 2) { pr = __ldg(args.idxP + r); kr = __ldg(args.idxK + r); }
            #pragma unroll
            for (int nf = 0; nf < 4; nf++) {
                int col = colBase + wn * 32 + nf * 8 + (lane & 3) * 2;
                float v0 = acc[mf * 16 + nf * 4 + half * 2 + 0];
                float v1 = acc[mf * 16 + nf * 4 + half * 2 + 1];
                if (EPI == 0) {
                    *(float2*)(args.outF + (size_t)r * 256 + col) = make_float2(v0, v1);
                } else if (EPI == 1) {
                    union { __half h[2]; uint32_t u; } t;
                    t.h[0] = __float2half_rn(tanhf(v0));
                    t.h[1] = __float2half_rn(tanhf(v1));
                    *(uint32_t*)(args.T + (size_t)r * 768 + col) = t.u;
                } else {
                    float x0 = v0 + __ldg(args.lb + col);
                    float x1 = v1 + __ldg(args.lb + col + 1);
                    x0 = (x0 > 0.0f) ? x0 : 0.01f * x0;
                    x1 = (x1 > 0.0f) ? x1 : 0.01f * x1;
                    x0 += __ldg(args.bias + col);
                    x1 += __ldg(args.bias + col + 1);
                    float2 v = make_float2(x0, x1);
                    *(float2*)(args.outF + (size_t)pr * 256 + col) = v;
                    *(float2*)(args.outF + (size_t)(args.Nfull + kr) * 256 + col) = v;
                }
            }
        }
    }
}

// ---------------------------------------------------------------------------
// prep_all: weights (transpose+split) + all input fp16 casts in one launch
// ---------------------------------------------------------------------------
__global__ void prep_all(const float* __restrict__ wo, const float* __restrict__ wp,
                         const float* __restrict__ wk, const float* __restrict__ lw,
                         const float* __restrict__ hp, const float* __restrict__ hk,
                         const float* __restrict__ ho, const int* __restrict__ idxP,
                         __half* __restrict__ Whi, __half* __restrict__ Wlo,
                         __half* __restrict__ Lhi, __half* __restrict__ Llo,
                         __half* __restrict__ Ahp, __half* __restrict__ Ahk,
                         __half* __restrict__ Aho, int N, int M)
{
    int idx = blockIdx.x * blockDim.x + threadIdx.x;
    const int R0 = 3 * 65536;
    const int R1 = R0 + 256 * 768;
    const int R2 = R1 + N * 32;
    const int R3 = R2 + N * 32;
    const int R4 = R3 + M * 32;
    if (idx < R0) {
        int wi = idx >> 16;
        int e = idx & 65535;
        int k = e >> 8, n = e & 255;
        const float* W = (wi == 0) ? wo : ((wi == 1) ? wp : wk);
        float v = W[k * 256 + n];
        __half h, l;
        split_h(v, h, l);
        Whi[wi * 65536 + n * 256 + k] = h;
        Wlo[wi * 65536 + n * 256 + k] = l;
    } else if (idx < R1) {
        int e = idx - R0;
        __half h, l;
        split_h(lw[e], h, l);
        Lhi[e] = h;
        Llo[e] = l;
    } else if (idx < R4) {
        const float* src;
        __half* dst;
        int r, j8;
        if (idx < R2) {
            int e = idx - R1; r = e >> 5; j8 = (e & 31) * 8; src = hp + (size_t)r * 256 + j8; dst = Ahp;
        } else if (idx < R3) {
            int e = idx - R2; r = e >> 5; j8 = (e & 31) * 8; src = hk + (size_t)r * 256 + j8; dst = Ahk;
        } else {
            int e = idx - R3; r = e >> 5; j8 = (e & 31) * 8;
            src = ho + (size_t)__ldg(idxP + r) * 256 + j8; dst = Aho;
        }
        float4 v0 = *(const float4*)src;
        float4 v1 = *(const float4*)(src + 4);
        union { __half h[8]; uint4 u; } t;
        t.h[0] = __float2half_rn(v0.x); t.h[1] = __float2half_rn(v0.y);
        t.h[2] = __float2half_rn(v0.z); t.h[3] = __float2half_rn(v0.w);
        t.h[4] = __float2half_rn(v1.x); t.h[5] = __float2half_rn(v1.y);
        t.h[6] = __float2half_rn(v1.z); t.h[7] = __float2half_rn(v1.w);
        *(uint4*)(dst + (size_t)r * 256 + j8) = t.u;
    }
}

// gather trans rows, tanh -> T fp16 cols [256:512),[512:768)
__global__ void gather_tanh_k(const float* __restrict__ out,
                              const int* __restrict__ idxP,
                              const int* __restrict__ idxK,
                              __half* __restrict__ T,
                              int Mr, int Nr)
{
    int idx = blockIdx.x * blockDim.x + threadIdx.x;
    int m = idx >> 6;
    int part = idx & 63;
    if (m >= Mr) return;
    const float* src;
    int dcol;
    if (part < 32) {
        int p = __ldg(idxP + m);
        src = out + (size_t)p * 256 + part * 8;
        dcol = 256 + part * 8;
    } else {
        int kq = __ldg(idxK + m);
        src = out + (size_t)Nr * 256 + (size_t)kq * 256 + (part - 32) * 8;
        dcol = 512 + (part - 32) * 8;
    }
    float4 v0 = *(const float4*)src;
    float4 v1 = *(const float4*)(src + 4);
    union { __half h[8]; uint4 u; } t;
    t.h[0] = __float2half_rn(tanhf(v0.x)); t.h[1] = __float2half_rn(tanhf(v0.y));
    t.h[2] = __float2half_rn(tanhf(v0.z)); t.h[3] = __float2half_rn(tanhf(v0.w));
    t.h[4] = __float2half_rn(tanhf(v1.x)); t.h[5] = __float2half_rn(tanhf(v1.y));
    t.h[6] = __float2half_rn(tanhf(v1.z)); t.h[7] = __float2half_rn(tanhf(v1.w));
    *(uint4*)(T + (size_t)m * 768 + dcol) = t.u;
}

extern "C" void kernel_launch(void* const* d_in, const int* in_sizes, int n_in,
                              void* d_out, int out_size)
{
    const float* h_p = (const float*)d_in[0];
    const float* h_k = (const float*)d_in[1];
    const float* h_o = (const float*)d_in[2];
    const int* idxP  = (const int*)d_in[3];
    const int* idxK  = (const int*)d_in[4];
    const float* w_o = (const float*)d_in[5];
    const float* w_p = (const float*)d_in[6];
    const float* w_k = (const float*)d_in[7];
    const float* lw  = (const float*)d_in[8];
    const float* lb  = (const float*)d_in[9];
    const float* bs  = (const float*)d_in[10];
    float* out = (float*)d_out;

    const int N = in_sizes[0] / DDIM;
    const int M = in_sizes[3];

    __half *Whi, *Wlo, *Lhi, *Llo, *T, *Ahp, *Ahk, *Aho;
    cudaGetSymbolAddress((void**)&Whi, g_Whi);
    cudaGetSymbolAddress((void**)&Wlo, g_Wlo);
    cudaGetSymbolAddress((void**)&Lhi, g_Lhi);
    cudaGetSymbolAddress((void**)&Llo, g_Llo);
    cudaGetSymbolAddress((void**)&T, g_T);
    cudaGetSymbolAddress((void**)&Ahp, g_Ahp);
    cudaGetSymbolAddress((void**)&Ahk, g_Ahk);
    cudaGetSymbolAddress((void**)&Aho, g_Aho);

    cudaFuncSetAttribute(mma_gemm<0, 256>, cudaFuncAttributeMaxDynamicSharedMemorySize, SMEM_BYTES);
    cudaFuncSetAttribute(mma_gemm<1, 256>, cudaFuncAttributeMaxDynamicSharedMemorySize, SMEM_BYTES);
    cudaFuncSetAttribute(mma_gemm<2, 768>, cudaFuncAttributeMaxDynamicSharedMemorySize, SMEM_BYTES);

    // 1. all prep in one launch
    {
        int total = 3 * 65536 + 256 * 768 + N * 32 + N * 32 + M * 32;
        prep_all<<<(total + 255) / 256, 256>>>(w_o, w_p, w_k, lw, h_p, h_k, h_o, idxP,
                                               Whi, Wlo, Lhi, Llo, Ahp, Ahk, Aho, N, M);
    }
    // 2. trans_hp / trans_hk GEMMs
    {
        dim3 grd((N + 127) / 128, 2);
        Args a = {};
        a.Ah = Ahp; a.Bhi = Whi + 1 * 65536; a.Blo = Wlo + 1 * 65536;
        a.outF = out; a.rowsC = N; a.Nfull = N;
        mma_gemm<0, 256><<<grd, 256, SMEM_BYTES>>>(a);
        Args b = {};
        b.Ah = Ahk; b.Bhi = Whi + 2 * 65536; b.Blo = Wlo + 2 * 65536;
        b.outF = out + (size_t)N * 256; b.rowsC = N; b.Nfull = N;
        mma_gemm<0, 256><<<grd, 256, SMEM_BYTES>>>(b);
    }
    // 3. gathered ho GEMM -> tanh -> T cols [0:256)
    {
        dim3 grd((M + 127) / 128, 2);
        Args a = {};
        a.Ah = Aho; a.Bhi = Whi + 0 * 65536; a.Blo = Wlo + 0 * 65536;
        a.T = T; a.rowsC = M; a.Nfull = N;
        mma_gemm<1, 256><<<grd, 256, SMEM_BYTES>>>(a);
    }
    // 4. gather + tanh of trans rows -> T cols [256:768)
    gather_tanh_k<<<(M * 64 + 255) / 256, 256>>>(out, idxP, idxK, T, M, N);
    // 5. final linear (K=768) + leaky + bias + scatter
    {
        dim3 grd((M + 127) / 128, 2);
        Args a = {};
        a.Ah = T; a.Bhi = Lhi; a.Blo = Llo;
        a.outF = out; a.idxP = idxP; a.idxK = idxK; a.lb = lb; a.bias = bs;
        a.rowsC = M; a.Nfull = N;
        mma_gemm<2, 768><<<grd, 256, SMEM_BYTES>>>(a);
    }
}

// round 10
// speedup vs baseline: 5.3694x; 1.4335x over previous
#include <cuda_runtime.h>
#include <cuda_fp16.h>
#include <math.h>
#include <stdint.h>

#define DDIM 256
#define NMAX 100000
#define MMAX 50000

// ---------------- device scratch (static; no runtime allocs) ---------------
__device__ __half g_W[3 * 256 * 256];       // transposed [n][k] fp16
__device__ __half g_L[256 * 768];           // linear_w [n][k] fp16
__device__ __half g_T[(size_t)MMAX * 768];  // tanh concat (A of final GEMM)
__device__ __half g_Ahp[(size_t)NMAX * 256];
__device__ __half g_Ahk[(size_t)NMAX * 256];
__device__ __half g_Aho[(size_t)MMAX * 256];

// ---------------- helpers --------------------------------------------------
__device__ __forceinline__ uint32_t smem_u32(const void* p) {
    uint32_t a;
    asm("{ .reg .u64 t; cvta.to.shared.u64 t, %1; cvt.u32.u64 %0, t; }" : "=r"(a) : "l"(p));
    return a;
}
__device__ __forceinline__ void ldmx4(uint32_t& r0, uint32_t& r1, uint32_t& r2, uint32_t& r3,
                                      uint32_t addr) {
    asm volatile("ldmatrix.sync.aligned.m8n8.x4.shared.b16 {%0,%1,%2,%3}, [%4];"
                 : "=r"(r0), "=r"(r1), "=r"(r2), "=r"(r3) : "r"(addr));
}
__device__ __forceinline__ void mma16816(float* d, uint32_t a0, uint32_t a1, uint32_t a2,
                                         uint32_t a3, uint32_t b0, uint32_t b1) {
    asm volatile(
        "mma.sync.aligned.m16n8k16.row.col.f32.f16.f16.f32 "
        "{%0,%1,%2,%3}, {%4,%5,%6,%7}, {%8,%9}, {%0,%1,%2,%3};"
        : "+f"(d[0]), "+f"(d[1]), "+f"(d[2]), "+f"(d[3])
        : "r"(a0), "r"(a1), "r"(a2), "r"(a3), "r"(b0), "r"(b1));
}
__device__ __forceinline__ void cp_async16(uint32_t dst, const void* src, bool pred) {
    int sz = pred ? 16 : 0;
    asm volatile("cp.async.cg.shared.global [%0], [%1], 16, %2;"
                 :: "r"(dst), "l"(src), "r"(sz));
}
#define CP_COMMIT()  asm volatile("cp.async.commit_group;" ::: "memory")
#define CP_WAIT_ALL() asm volatile("cp.async.wait_group 0;" ::: "memory")
#define SW128(o) ((o) ^ (((o) >> 3) & 0x70))

// smem: 2 buffers of {A 16KB, B 16KB}
#define BUF_STRIDE 32768
#define OFF_A 0
#define OFF_B 16384
#define SMEM_BYTES (2 * BUF_STRIDE)

struct Args {
    const __half* Ah;
    const __half* B;
    float* outF;
    __half* T;
    const int* idxP;
    const int* idxK;
    const float* lb;
    const float* bias;
    int rowsC;
    int Nfull;
};

// EPI: 0 = store fp32 rows; 1 = tanh -> T fp16 cols [0:256); 2 = +lb, leaky, +bias, scatter
template<int EPI, int KDIM>
__global__ void __launch_bounds__(256, 2)
mma_gemm(const Args args)
{
    extern __shared__ char smem[];
    const uint32_t sb = smem_u32(smem);
    const int tid = threadIdx.x;
    const int w = tid >> 5;
    const int lane = tid & 31;
    const int rowBase = blockIdx.x * 128;
    const int colBase = blockIdx.y * 128;
    const int rowsC = args.rowsC;

    const int wm = w & 1;
    const int wn = w >> 1;

    float acc[64];
    #pragma unroll
    for (int i = 0; i < 64; i++) acc[i] = 0.0f;

    // per-thread cp.async geometry (16B granules; 8 threads per 64-fp16 row)
    const int lr = tid >> 3;            // 0..31, row step 32
    const int lj8 = (tid & 7) * 8;      // k offset within chunk
    const uint32_t soA[4] = {
        SW128((uint32_t)((lr + 0) * 128 + lj8 * 2)),
        SW128((uint32_t)((lr + 32) * 128 + lj8 * 2)),
        SW128((uint32_t)((lr + 64) * 128 + lj8 * 2)),
        SW128((uint32_t)((lr + 96) * 128 + lj8 * 2))};

    const int NCH = KDIM / 64;

    auto issue_chunk = [&](int c) {
        const int k0 = c * 64;
        const uint32_t bufb = sb + (uint32_t)(c & 1) * BUF_STRIDE;
        #pragma unroll
        for (int i = 0; i < 4; i++) {
            int gr = rowBase + lr + i * 32;
            bool ok = (gr < rowsC);
            const __half* src = args.Ah + (size_t)(ok ? gr : 0) * KDIM + k0 + lj8;
            cp_async16(bufb + OFF_A + soA[i], src, ok);
        }
        #pragma unroll
        for (int i = 0; i < 4; i++) {
            int n = lr + i * 32;
            size_t off = (size_t)(colBase + n) * KDIM + k0 + lj8;
            cp_async16(bufb + OFF_B + soA[i], args.B + off, true);
        }
        CP_COMMIT();
    };

    // ldmatrix address precompute
    // B fused x4 covering nf-pair (16 n-rows): lanes 0-15 -> rows nf*8..+7 (k0|k16),
    // lanes 16-31 -> rows nf*8+8..+15 (k0|k16)
    const int bnrow = wn * 32 + ((lane >> 4) & 1) * 8 + (lane & 7);
    const uint32_t bcol16 = (uint32_t)(((lane >> 3) & 1) * 16);
    // A x4: lanes 0-15 rows m..m+15 col ks*32, lanes 16-31 same rows col +16
    const int amrow = wm * 64 + (lane & 15);
    const uint32_t acol16 = (uint32_t)((lane >> 4) * 16);

    issue_chunk(0);

    for (int c = 0; c < NCH; c++) {
        CP_WAIT_ALL();
        __syncthreads();
        if (c + 1 < NCH) issue_chunk(c + 1);

        const uint32_t bufb = sb + (uint32_t)(c & 1) * BUF_STRIDE;
        #pragma unroll
        for (int ks = 0; ks < 4; ks++) {
            uint32_t b[4][2];
            uint32_t a[4][4];
            #pragma unroll
            for (int np = 0; np < 2; np++) {   // nf pairs {0,1}, {2,3}
                uint32_t ad = bufb + OFF_B +
                    SW128((uint32_t)((bnrow + np * 16) * 128) + (uint32_t)(ks * 32) + bcol16);
                ldmx4(b[np * 2][0], b[np * 2][1], b[np * 2 + 1][0], b[np * 2 + 1][1], ad);
            }
            #pragma unroll
            for (int mf = 0; mf < 4; mf++) {
                uint32_t ad = bufb + OFF_A +
                    SW128((uint32_t)((amrow + mf * 16) * 128) + (uint32_t)(ks * 32) + acol16);
                ldmx4(a[mf][0], a[mf][1], a[mf][2], a[mf][3], ad);
            }
            #pragma unroll
            for (int mf = 0; mf < 4; mf++)
                #pragma unroll
                for (int nf = 0; nf < 4; nf++)
                    mma16816(&acc[mf * 16 + nf * 4],
                             a[mf][0], a[mf][1], a[mf][2], a[mf][3],
                             b[nf][0], b[nf][1]);
        }
    }

    // ---- epilogue ----
    #pragma unroll
    for (int mf = 0; mf < 4; mf++) {
        int r0 = rowBase + wm * 64 + mf * 16 + (lane >> 2);
        #pragma unroll
        for (int half = 0; half < 2; half++) {
            int r = r0 + half * 8;
            if (r >= rowsC) continue;
            int pr = 0, kr = 0;
            if (EPI == 2) { pr = __ldg(args.idxP + r); kr = __ldg(args.idxK + r); }
            #pragma unroll
            for (int nf = 0; nf < 4; nf++) {
                int col = colBase + wn * 32 + nf * 8 + (lane & 3) * 2;
                float v0 = acc[mf * 16 + nf * 4 + half * 2 + 0];
                float v1 = acc[mf * 16 + nf * 4 + half * 2 + 1];
                if (EPI == 0) {
                    *(float2*)(args.outF + (size_t)r * 256 + col) = make_float2(v0, v1);
                } else if (EPI == 1) {
                    union { __half h[2]; uint32_t u; } t;
                    t.h[0] = __float2half_rn(tanhf(v0));
                    t.h[1] = __float2half_rn(tanhf(v1));
                    *(uint32_t*)(args.T + (size_t)r * 768 + col) = t.u;
                } else {
                    float x0 = v0 + __ldg(args.lb + col);
                    float x1 = v1 + __ldg(args.lb + col + 1);
                    x0 = (x0 > 0.0f) ? x0 : 0.01f * x0;
                    x1 = (x1 > 0.0f) ? x1 : 0.01f * x1;
                    x0 += __ldg(args.bias + col);
                    x1 += __ldg(args.bias + col + 1);
                    float2 v = make_float2(x0, x1);
                    *(float2*)(args.outF + (size_t)pr * 256 + col) = v;
                    *(float2*)(args.outF + (size_t)(args.Nfull + kr) * 256 + col) = v;
                }
            }
        }
    }
}

// ---------------------------------------------------------------------------
// prep_all: weights (transpose, fp16) + linear_w (fp16) + input fp16 casts
// ---------------------------------------------------------------------------
__global__ void prep_all(const float* __restrict__ wo, const float* __restrict__ wp,
                         const float* __restrict__ wk, const float* __restrict__ lw,
                         const float* __restrict__ hp, const float* __restrict__ hk,
                         const float* __restrict__ ho, const int* __restrict__ idxP,
                         __half* __restrict__ W, __half* __restrict__ L,
                         __half* __restrict__ Ahp, __half* __restrict__ Ahk,
                         __half* __restrict__ Aho, int N, int M)
{
    int idx = blockIdx.x * blockDim.x + threadIdx.x;
    const int R0 = 3 * 65536;
    const int R1 = R0 + 256 * 768;
    const int R2 = R1 + N * 32;
    const int R3 = R2 + N * 32;
    const int R4 = R3 + M * 32;
    if (idx < R0) {
        int wi = idx >> 16;
        int e = idx & 65535;
        int k = e >> 8, n = e & 255;
        const float* Wf = (wi == 0) ? wo : ((wi == 1) ? wp : wk);
        W[wi * 65536 + n * 256 + k] = __float2half_rn(Wf[k * 256 + n]);
    } else if (idx < R1) {
        int e = idx - R0;
        L[e] = __float2half_rn(lw[e]);
    } else if (idx < R4) {
        const float* src;
        __half* dst;
        int r, j8;
        if (idx < R2) {
            int e = idx - R1; r = e >> 5; j8 = (e & 31) * 8; src = hp + (size_t)r * 256 + j8; dst = Ahp;
        } else if (idx < R3) {
            int e = idx - R2; r = e >> 5; j8 = (e & 31) * 8; src = hk + (size_t)r * 256 + j8; dst = Ahk;
        } else {
            int e = idx - R3; r = e >> 5; j8 = (e & 31) * 8;
            src = ho + (size_t)__ldg(idxP + r) * 256 + j8; dst = Aho;
        }
        float4 v0 = *(const float4*)src;
        float4 v1 = *(const float4*)(src + 4);
        union { __half h[8]; uint4 u; } t;
        t.h[0] = __float2half_rn(v0.x); t.h[1] = __float2half_rn(v0.y);
        t.h[2] = __float2half_rn(v0.z); t.h[3] = __float2half_rn(v0.w);
        t.h[4] = __float2half_rn(v1.x); t.h[5] = __float2half_rn(v1.y);
        t.h[6] = __float2half_rn(v1.z); t.h[7] = __float2half_rn(v1.w);
        *(uint4*)(dst + (size_t)r * 256 + j8) = t.u;
    }
}

// gather trans rows, tanh -> T fp16 cols [256:512),[512:768)
__global__ void gather_tanh_k(const float* __restrict__ out,
                              const int* __restrict__ idxP,
                              const int* __restrict__ idxK,
                              __half* __restrict__ T,
                              int Mr, int Nr)
{
    int idx = blockIdx.x * blockDim.x + threadIdx.x;
    int m = idx >> 6;
    int part = idx & 63;
    if (m >= Mr) return;
    const float* src;
    int dcol;
    if (part < 32) {
        int p = __ldg(idxP + m);
        src = out + (size_t)p * 256 + part * 8;
        dcol = 256 + part * 8;
    } else {
        int kq = __ldg(idxK + m);
        src = out + (size_t)Nr * 256 + (size_t)kq * 256 + (part - 32) * 8;
        dcol = 512 + (part - 32) * 8;
    }
    float4 v0 = *(const float4*)src;
    float4 v1 = *(const float4*)(src + 4);
    union { __half h[8]; uint4 u; } t;
    t.h[0] = __float2half_rn(tanhf(v0.x)); t.h[1] = __float2half_rn(tanhf(v0.y));
    t.h[2] = __float2half_rn(tanhf(v0.z)); t.h[3] = __float2half_rn(tanhf(v0.w));
    t.h[4] = __float2half_rn(tanhf(v1.x)); t.h[5] = __float2half_rn(tanhf(v1.y));
    t.h[6] = __float2half_rn(tanhf(v1.z)); t.h[7] = __float2half_rn(tanhf(v1.w));
    *(uint4*)(T + (size_t)m * 768 + dcol) = t.u;
}

extern "C" void kernel_launch(void* const* d_in, const int* in_sizes, int n_in,
                              void* d_out, int out_size)
{
    const float* h_p = (const float*)d_in[0];
    const float* h_k = (const float*)d_in[1];
    const float* h_o = (const float*)d_in[2];
    const int* idxP  = (const int*)d_in[3];
    const int* idxK  = (const int*)d_in[4];
    const float* w_o = (const float*)d_in[5];
    const float* w_p = (const float*)d_in[6];
    const float* w_k = (const float*)d_in[7];
    const float* lw  = (const float*)d_in[8];
    const float* lb  = (const float*)d_in[9];
    const float* bs  = (const float*)d_in[10];
    float* out = (float*)d_out;

    const int N = in_sizes[0] / DDIM;
    const int M = in_sizes[3];

    __half *W, *L, *T, *Ahp, *Ahk, *Aho;
    cudaGetSymbolAddress((void**)&W, g_W);
    cudaGetSymbolAddress((void**)&L, g_L);
    cudaGetSymbolAddress((void**)&T, g_T);
    cudaGetSymbolAddress((void**)&Ahp, g_Ahp);
    cudaGetSymbolAddress((void**)&Ahk, g_Ahk);
    cudaGetSymbolAddress((void**)&Aho, g_Aho);

    cudaFuncSetAttribute(mma_gemm<0, 256>, cudaFuncAttributeMaxDynamicSharedMemorySize, SMEM_BYTES);
    cudaFuncSetAttribute(mma_gemm<1, 256>, cudaFuncAttributeMaxDynamicSharedMemorySize, SMEM_BYTES);
    cudaFuncSetAttribute(mma_gemm<2, 768>, cudaFuncAttributeMaxDynamicSharedMemorySize, SMEM_BYTES);

    // 1. all prep in one launch
    {
        int total = 3 * 65536 + 256 * 768 + N * 32 + N * 32 + M * 32;
        prep_all<<<(total + 255) / 256, 256>>>(w_o, w_p, w_k, lw, h_p, h_k, h_o, idxP,
                                               W, L, Ahp, Ahk, Aho, N, M);
    }
    // 2. trans_hp / trans_hk GEMMs
    {
        dim3 grd((N + 127) / 128, 2);
        Args a = {};
        a.Ah = Ahp; a.B = W + 1 * 65536;
        a.outF = out; a.rowsC = N; a.Nfull = N;
        mma_gemm<0, 256><<<grd, 256, SMEM_BYTES>>>(a);
        Args b = {};
        b.Ah = Ahk; b.B = W + 2 * 65536;
        b.outF = out + (size_t)N * 256; b.rowsC = N; b.Nfull = N;
        mma_gemm<0, 256><<<grd, 256, SMEM_BYTES>>>(b);
    }
    // 3. gathered ho GEMM -> tanh -> T cols [0:256)
    {
        dim3 grd((M + 127) / 128, 2);
        Args a = {};
        a.Ah = Aho; a.B = W + 0 * 65536;
        a.T = T; a.rowsC = M; a.Nfull = N;
        mma_gemm<1, 256><<<grd, 256, SMEM_BYTES>>>(a);
    }
    // 4. gather + tanh of trans rows -> T cols [256:768)
    gather_tanh_k<<<(M * 64 + 255) / 256, 256>>>(out, idxP, idxK, T, M, N);
    // 5. final linear (K=768) + leaky + bias + scatter
    {
        dim3 grd((M + 127) / 128, 2);
        Args a = {};
        a.Ah = T; a.B = L;
        a.outF = out; a.idxP = idxP; a.idxK = idxK; a.lb = lb; a.bias = bs;
        a.rowsC = M; a.Nfull = N;
        mma_gemm<2, 768><<<grd, 256, SMEM_BYTES>>>(a);
    }
}

// round 11
// speedup vs baseline: 5.5621x; 1.0359x over previous
#include <cuda_runtime.h>
#include <cuda_fp16.h>
#include <math.h>
#include <stdint.h>

#define DDIM 256
#define NMAX 100000
#define MMAX 50000

// ---------------- device scratch (static; no runtime allocs) ---------------
__device__ __half g_W[3 * 256 * 256];       // transposed [n][k] fp16 (o,p,k)
__device__ __half g_L[256 * 768];           // linear_w [n][k] fp16
__device__ __half g_T[(size_t)MMAX * 768];  // tanh concat (A of final GEMM)
__device__ __half g_Ahp[(size_t)NMAX * 256];
__device__ __half g_Ahk[(size_t)NMAX * 256];
__device__ __half g_Aho[(size_t)MMAX * 256];
__device__ int    g_invP[NMAX];
__device__ int    g_invK[NMAX];

// ---------------- helpers --------------------------------------------------
__device__ __forceinline__ uint32_t smem_u32(const void* p) {
    uint32_t a;
    asm("{ .reg .u64 t; cvta.to.shared.u64 t, %1; cvt.u32.u64 %0, t; }" : "=r"(a) : "l"(p));
    return a;
}
__device__ __forceinline__ void ldmx4(uint32_t& r0, uint32_t& r1, uint32_t& r2, uint32_t& r3,
                                      uint32_t addr) {
    asm volatile("ldmatrix.sync.aligned.m8n8.x4.shared.b16 {%0,%1,%2,%3}, [%4];"
                 : "=r"(r0), "=r"(r1), "=r"(r2), "=r"(r3) : "r"(addr));
}
__device__ __forceinline__ void mma16816(float* d, uint32_t a0, uint32_t a1, uint32_t a2,
                                         uint32_t a3, uint32_t b0, uint32_t b1) {
    asm volatile(
        "mma.sync.aligned.m16n8k16.row.col.f32.f16.f16.f32 "
        "{%0,%1,%2,%3}, {%4,%5,%6,%7}, {%8,%9}, {%0,%1,%2,%3};"
        : "+f"(d[0]), "+f"(d[1]), "+f"(d[2]), "+f"(d[3])
        : "r"(a0), "r"(a1), "r"(a2), "r"(a3), "r"(b0), "r"(b1));
}
__device__ __forceinline__ void cp_async16(uint32_t dst, const void* src, bool pred) {
    int sz = pred ? 16 : 0;
    asm volatile("cp.async.cg.shared.global [%0], [%1], 16, %2;"
                 :: "r"(dst), "l"(src), "r"(sz));
}
#define CP_COMMIT()  asm volatile("cp.async.commit_group;" ::: "memory")
#define CP_WAIT_ALL() asm volatile("cp.async.wait_group 0;" ::: "memory")
#define SW128(o) ((o) ^ (((o) >> 3) & 0x70))

// smem: 2 buffers of {A 16KB, B 16KB}
#define BUF_STRIDE 32768
#define OFF_A 0
#define OFF_B 16384
#define SMEM_BYTES (2 * BUF_STRIDE)

// ---------------------------------------------------------------------------
// mega GEMM: z=0 hp, z=1 hk (write out + cond tanh->T), z=2 ho (tanh->T)
// ---------------------------------------------------------------------------
struct Args3 {
    const __half* A0; const __half* A1; const __half* A2;
    const __half* B0; const __half* B1; const __half* B2;
    float* outF;
    __half* T;
    const int* invP;
    const int* invK;
    int N;
    int M;
};

__global__ void __launch_bounds__(256, 2)
gemm3(const Args3 args)
{
    extern __shared__ char smem[];
    const uint32_t sb = smem_u32(smem);
    const int tid = threadIdx.x;
    const int w = tid >> 5;
    const int lane = tid & 31;
    const int z = blockIdx.z;
    const int rowBase = blockIdx.x * 128;
    const int colBase = blockIdx.y * 128;
    const int rowsC = (z == 2) ? args.M : args.N;
    if (rowBase >= rowsC) return;

    const __half* Ah = (z == 0) ? args.A0 : ((z == 1) ? args.A1 : args.A2);
    const __half* B  = (z == 0) ? args.B0 : ((z == 1) ? args.B1 : args.B2);

    const int wm = w & 1;
    const int wn = w >> 1;

    float acc[64];
    #pragma unroll
    for (int i = 0; i < 64; i++) acc[i] = 0.0f;

    const int lr = tid >> 3;
    const int lj8 = (tid & 7) * 8;
    const uint32_t soA[4] = {
        SW128((uint32_t)((lr + 0) * 128 + lj8 * 2)),
        SW128((uint32_t)((lr + 32) * 128 + lj8 * 2)),
        SW128((uint32_t)((lr + 64) * 128 + lj8 * 2)),
        SW128((uint32_t)((lr + 96) * 128 + lj8 * 2))};

    auto issue_chunk = [&](int c) {
        const int k0 = c * 64;
        const uint32_t bufb = sb + (uint32_t)(c & 1) * BUF_STRIDE;
        #pragma unroll
        for (int i = 0; i < 4; i++) {
            int gr = rowBase + lr + i * 32;
            bool ok = (gr < rowsC);
            const __half* src = Ah + (size_t)(ok ? gr : 0) * 256 + k0 + lj8;
            cp_async16(bufb + OFF_A + soA[i], src, ok);
        }
        #pragma unroll
        for (int i = 0; i < 4; i++) {
            int n = lr + i * 32;
            size_t off = (size_t)(colBase + n) * 256 + k0 + lj8;
            cp_async16(bufb + OFF_B + soA[i], B + off, true);
        }
        CP_COMMIT();
    };

    const int bnrow = wn * 32 + ((lane >> 4) & 1) * 8 + (lane & 7);
    const uint32_t bcol16 = (uint32_t)(((lane >> 3) & 1) * 16);
    const int amrow = wm * 64 + (lane & 15);
    const uint32_t acol16 = (uint32_t)((lane >> 4) * 16);

    issue_chunk(0);

    for (int c = 0; c < 4; c++) {
        CP_WAIT_ALL();
        __syncthreads();
        if (c + 1 < 4) issue_chunk(c + 1);

        const uint32_t bufb = sb + (uint32_t)(c & 1) * BUF_STRIDE;
        #pragma unroll
        for (int ks = 0; ks < 4; ks++) {
            uint32_t b[4][2];
            uint32_t a[4][4];
            #pragma unroll
            for (int np = 0; np < 2; np++) {
                uint32_t ad = bufb + OFF_B +
                    SW128((uint32_t)((bnrow + np * 16) * 128) + (uint32_t)(ks * 32) + bcol16);
                ldmx4(b[np * 2][0], b[np * 2][1], b[np * 2 + 1][0], b[np * 2 + 1][1], ad);
            }
            #pragma unroll
            for (int mf = 0; mf < 4; mf++) {
                uint32_t ad = bufb + OFF_A +
                    SW128((uint32_t)((amrow + mf * 16) * 128) + (uint32_t)(ks * 32) + acol16);
                ldmx4(a[mf][0], a[mf][1], a[mf][2], a[mf][3], ad);
            }
            #pragma unroll
            for (int mf = 0; mf < 4; mf++)
                #pragma unroll
                for (int nf = 0; nf < 4; nf++)
                    mma16816(&acc[mf * 16 + nf * 4],
                             a[mf][0], a[mf][1], a[mf][2], a[mf][3],
                             b[nf][0], b[nf][1]);
        }
    }

    // ---- epilogue ----
    float* outBase = (z == 1) ? (args.outF + (size_t)args.N * 256) : args.outF;
    const int* inv = (z == 0) ? args.invP : args.invK;
    const int tcolOff = (z == 0) ? 256 : ((z == 1) ? 512 : 0);

    #pragma unroll
    for (int mf = 0; mf < 4; mf++) {
        int r0 = rowBase + wm * 64 + mf * 16 + (lane >> 2);
        #pragma unroll
        for (int half = 0; half < 2; half++) {
            int r = r0 + half * 8;
            if (r >= rowsC) continue;
            int tm = (z == 2) ? r : __ldg(inv + r);
            #pragma unroll
            for (int nf = 0; nf < 4; nf++) {
                int col = colBase + wn * 32 + nf * 8 + (lane & 3) * 2;
                float v0 = acc[mf * 16 + nf * 4 + half * 2 + 0];
                float v1 = acc[mf * 16 + nf * 4 + half * 2 + 1];
                if (z != 2) {
                    *(float2*)(outBase + (size_t)r * 256 + col) = make_float2(v0, v1);
                }
                if (tm >= 0) {
                    union { __half h[2]; uint32_t u; } t;
                    t.h[0] = __float2half_rn(tanhf(v0));
                    t.h[1] = __float2half_rn(tanhf(v1));
                    *(uint32_t*)(args.T + (size_t)tm * 768 + tcolOff + col) = t.u;
                }
            }
        }
    }
}

// ---------------------------------------------------------------------------
// final GEMM: K=768, +lb, leaky, +bias, scatter to out rows idxP / N+idxK
// ---------------------------------------------------------------------------
struct ArgsF {
    const __half* Ah;
    const __half* B;
    float* outF;
    const int* idxP;
    const int* idxK;
    const float* lb;
    const float* bias;
    int rowsC;
    int Nfull;
};

__global__ void __launch_bounds__(256, 2)
gemm_final(const ArgsF args)
{
    extern __shared__ char smem[];
    const uint32_t sb = smem_u32(smem);
    const int tid = threadIdx.x;
    const int w = tid >> 5;
    const int lane = tid & 31;
    const int rowBase = blockIdx.x * 128;
    const int colBase = blockIdx.y * 128;
    const int rowsC = args.rowsC;

    const int wm = w & 1;
    const int wn = w >> 1;

    float acc[64];
    #pragma unroll
    for (int i = 0; i < 64; i++) acc[i] = 0.0f;

    const int lr = tid >> 3;
    const int lj8 = (tid & 7) * 8;
    const uint32_t soA[4] = {
        SW128((uint32_t)((lr + 0) * 128 + lj8 * 2)),
        SW128((uint32_t)((lr + 32) * 128 + lj8 * 2)),
        SW128((uint32_t)((lr + 64) * 128 + lj8 * 2)),
        SW128((uint32_t)((lr + 96) * 128 + lj8 * 2))};

    auto issue_chunk = [&](int c) {
        const int k0 = c * 64;
        const uint32_t bufb = sb + (uint32_t)(c & 1) * BUF_STRIDE;
        #pragma unroll
        for (int i = 0; i < 4; i++) {
            int gr = rowBase + lr + i * 32;
            bool ok = (gr < rowsC);
            const __half* src = args.Ah + (size_t)(ok ? gr : 0) * 768 + k0 + lj8;
            cp_async16(bufb + OFF_A + soA[i], src, ok);
        }
        #pragma unroll
        for (int i = 0; i < 4; i++) {
            int n = lr + i * 32;
            size_t off = (size_t)(colBase + n) * 768 + k0 + lj8;
            cp_async16(bufb + OFF_B + soA[i], args.B + off, true);
        }
        CP_COMMIT();
    };

    const int bnrow = wn * 32 + ((lane >> 4) & 1) * 8 + (lane & 7);
    const uint32_t bcol16 = (uint32_t)(((lane >> 3) & 1) * 16);
    const int amrow = wm * 64 + (lane & 15);
    const uint32_t acol16 = (uint32_t)((lane >> 4) * 16);

    issue_chunk(0);

    for (int c = 0; c < 12; c++) {
        CP_WAIT_ALL();
        __syncthreads();
        if (c + 1 < 12) issue_chunk(c + 1);

        const uint32_t bufb = sb + (uint32_t)(c & 1) * BUF_STRIDE;
        #pragma unroll
        for (int ks = 0; ks < 4; ks++) {
            uint32_t b[4][2];
            uint32_t a[4][4];
            #pragma unroll
            for (int np = 0; np < 2; np++) {
                uint32_t ad = bufb + OFF_B +
                    SW128((uint32_t)((bnrow + np * 16) * 128) + (uint32_t)(ks * 32) + bcol16);
                ldmx4(b[np * 2][0], b[np * 2][1], b[np * 2 + 1][0], b[np * 2 + 1][1], ad);
            }
            #pragma unroll
            for (int mf = 0; mf < 4; mf++) {
                uint32_t ad = bufb + OFF_A +
                    SW128((uint32_t)((amrow + mf * 16) * 128) + (uint32_t)(ks * 32) + acol16);
                ldmx4(a[mf][0], a[mf][1], a[mf][2], a[mf][3], ad);
            }
            #pragma unroll
            for (int mf = 0; mf < 4; mf++)
                #pragma unroll
                for (int nf = 0; nf < 4; nf++)
                    mma16816(&acc[mf * 16 + nf * 4],
                             a[mf][0], a[mf][1], a[mf][2], a[mf][3],
                             b[nf][0], b[nf][1]);
        }
    }

    #pragma unroll
    for (int mf = 0; mf < 4; mf++) {
        int r0 = rowBase + wm * 64 + mf * 16 + (lane >> 2);
        #pragma unroll
        for (int half = 0; half < 2; half++) {
            int r = r0 + half * 8;
            if (r >= rowsC) continue;
            int pr = __ldg(args.idxP + r);
            int kr = __ldg(args.idxK + r);
            #pragma unroll
            for (int nf = 0; nf < 4; nf++) {
                int col = colBase + wn * 32 + nf * 8 + (lane & 3) * 2;
                float x0 = acc[mf * 16 + nf * 4 + half * 2 + 0] + __ldg(args.lb + col);
                float x1 = acc[mf * 16 + nf * 4 + half * 2 + 1] + __ldg(args.lb + col + 1);
                x0 = (x0 > 0.0f) ? x0 : 0.01f * x0;
                x1 = (x1 > 0.0f) ? x1 : 0.01f * x1;
                x0 += __ldg(args.bias + col);
                x1 += __ldg(args.bias + col + 1);
                float2 v = make_float2(x0, x1);
                *(float2*)(args.outF + (size_t)pr * 256 + col) = v;
                *(float2*)(args.outF + (size_t)(args.Nfull + kr) * 256 + col) = v;
            }
        }
    }
}

// ---------------------------------------------------------------------------
__global__ void init_inv(int* __restrict__ invP, int* __restrict__ invK, int N)
{
    int i = blockIdx.x * blockDim.x + threadIdx.x;
    if (i < N) { invP[i] = -1; invK[i] = -1; }
}

__global__ void prep_all(const float* __restrict__ wo, const float* __restrict__ wp,
                         const float* __restrict__ wk, const float* __restrict__ lw,
                         const float* __restrict__ hp, const float* __restrict__ hk,
                         const float* __restrict__ ho,
                         const int* __restrict__ idxP, const int* __restrict__ idxK,
                         __half* __restrict__ W, __half* __restrict__ L,
                         __half* __restrict__ Ahp, __half* __restrict__ Ahk,
                         __half* __restrict__ Aho,
                         int* __restrict__ invP, int* __restrict__ invK,
                         int N, int M)
{
    int idx = blockIdx.x * blockDim.x + threadIdx.x;
    const int R0 = 3 * 65536;
    const int R1 = R0 + 256 * 768;
    const int R2 = R1 + N * 32;
    const int R3 = R2 + N * 32;
    const int R4 = R3 + M * 32;
    const int R5 = R4 + M;            // invP scatter
    const int R6 = R5 + M;            // invK scatter
    if (idx < R0) {
        int wi = idx >> 16;
        int e = idx & 65535;
        int k = e >> 8, n = e & 255;
        const float* Wf = (wi == 0) ? wo : ((wi == 1) ? wp : wk);
        W[wi * 65536 + n * 256 + k] = __float2half_rn(Wf[k * 256 + n]);
    } else if (idx < R1) {
        int e = idx - R0;
        L[e] = __float2half_rn(lw[e]);
    } else if (idx < R4) {
        const float* src;
        __half* dst;
        int r, j8;
        if (idx < R2) {
            int e = idx - R1; r = e >> 5; j8 = (e & 31) * 8; src = hp + (size_t)r * 256 + j8; dst = Ahp;
        } else if (idx < R3) {
            int e = idx - R2; r = e >> 5; j8 = (e & 31) * 8; src = hk + (size_t)r * 256 + j8; dst = Ahk;
        } else {
            int e = idx - R3; r = e >> 5; j8 = (e & 31) * 8;
            src = ho + (size_t)__ldg(idxP + r) * 256 + j8; dst = Aho;
        }
        float4 v0 = *(const float4*)src;
        float4 v1 = *(const float4*)(src + 4);
        union { __half h[8]; uint4 u; } t;
        t.h[0] = __float2half_rn(v0.x); t.h[1] = __float2half_rn(v0.y);
        t.h[2] = __float2half_rn(v0.z); t.h[3] = __float2half_rn(v0.w);
        t.h[4] = __float2half_rn(v1.x); t.h[5] = __float2half_rn(v1.y);
        t.h[6] = __float2half_rn(v1.z); t.h[7] = __float2half_rn(v1.w);
        *(uint4*)(dst + (size_t)r * 256 + j8) = t.u;
    } else if (idx < R5) {
        int m = idx - R4;
        invP[__ldg(idxP + m)] = m;
    } else if (idx < R6) {
        int m = idx - R5;
        invK[__ldg(idxK + m)] = m;
    }
}

extern "C" void kernel_launch(void* const* d_in, const int* in_sizes, int n_in,
                              void* d_out, int out_size)
{
    const float* h_p = (const float*)d_in[0];
    const float* h_k = (const float*)d_in[1];
    const float* h_o = (const float*)d_in[2];
    const int* idxP  = (const int*)d_in[3];
    const int* idxK  = (const int*)d_in[4];
    const float* w_o = (const float*)d_in[5];
    const float* w_p = (const float*)d_in[6];
    const float* w_k = (const float*)d_in[7];
    const float* lw  = (const float*)d_in[8];
    const float* lb  = (const float*)d_in[9];
    const float* bs  = (const float*)d_in[10];
    float* out = (float*)d_out;

    const int N = in_sizes[0] / DDIM;
    const int M = in_sizes[3];

    __half *W, *L, *T, *Ahp, *Ahk, *Aho;
    int *invP, *invK;
    cudaGetSymbolAddress((void**)&W, g_W);
    cudaGetSymbolAddress((void**)&L, g_L);
    cudaGetSymbolAddress((void**)&T, g_T);
    cudaGetSymbolAddress((void**)&Ahp, g_Ahp);
    cudaGetSymbolAddress((void**)&Ahk, g_Ahk);
    cudaGetSymbolAddress((void**)&Aho, g_Aho);
    cudaGetSymbolAddress((void**)&invP, g_invP);
    cudaGetSymbolAddress((void**)&invK, g_invK);

    cudaFuncSetAttribute(gemm3, cudaFuncAttributeMaxDynamicSharedMemorySize, SMEM_BYTES);
    cudaFuncSetAttribute(gemm_final, cudaFuncAttributeMaxDynamicSharedMemorySize, SMEM_BYTES);

    // 1. init inverse maps
    init_inv<<<(N + 255) / 256, 256>>>(invP, invK, N);
    // 2. prep (weights, casts, gather-cast, inverse scatter)
    {
        int total = 3 * 65536 + 256 * 768 + N * 32 + N * 32 + M * 32 + 2 * M;
        prep_all<<<(total + 255) / 256, 256>>>(w_o, w_p, w_k, lw, h_p, h_k, h_o,
                                               idxP, idxK, W, L, Ahp, Ahk, Aho,
                                               invP, invK, N, M);
    }
    // 3. hp/hk/ho GEMMs in one launch; tanh->T fused via inverse maps
    {
        dim3 grd((N + 127) / 128, 2, 3);
        Args3 a = {};
        a.A0 = Ahp; a.A1 = Ahk; a.A2 = Aho;
        a.B0 = W + 1 * 65536; a.B1 = W + 2 * 65536; a.B2 = W + 0 * 65536;
        a.outF = out; a.T = T; a.invP = invP; a.invK = invK;
        a.N = N; a.M = M;
        gemm3<<<grd, 256, SMEM_BYTES>>>(a);
    }
    // 4. final linear (K=768) + leaky + bias + scatter
    {
        dim3 grd((M + 127) / 128, 2);
        ArgsF a = {};
        a.Ah = T; a.B = L;
        a.outF = out; a.idxP = idxP; a.idxK = idxK; a.lb = lb; a.bias = bs;
        a.rowsC = M; a.Nfull = N;
        gemm_final<<<grd, 256, SMEM_BYTES>>>(a);
    }
}